// round 3
// baseline (speedup 1.0000x reference)
#include <cuda_runtime.h>

namespace {

constexpr int NN  = 50000;   // nodes
constexpr int NE  = 800000;  // edges
constexpr int KIN = 256;     // in_dim
constexpr int NB  = (NN + 1023) / 1024;  // scan blocks = 49

// ---------------- scratch (static device memory; no allocations) ----------------
__device__ float g_h1[NN * 128];     // leaky(x@W_in+b_in)  (pre-BN1)
__device__ float g_t1[NN * 128];     // BN1(h1) @ W1
__device__ float g_skip[NN * 128];   // leaky(gat1 + bias1)
__device__ float g_t2[NN * 128];     // skip @ W2
__device__ float g_out2[NN * 128];   // gat2 + bias2
__device__ float g_as1[NN * 8];
__device__ float g_ad1[NN * 8];
__device__ float g_as2[NN];
__device__ float g_ad2[NN];
__device__ int   g_src[NE];
__device__ int   g_dst[NE];
__device__ int   g_eid[NE];          // edge ids sorted by dst (CSR)
__device__ int   g_deg[NN];
__device__ int   g_cur[NN];
__device__ int   g_rs[NN + 1];       // CSR row starts
__device__ int   g_bsum[NB];
__device__ int   g_boff[NB];
__device__ float g_stats1[256];      // [0:128) colsum, [128:256) colsumsq
__device__ float g_stats2[256];
__device__ float g_sc1[128], g_sh1[128], g_sc2[128], g_sh2[128];
__device__ int   g_is64;             // edge_index dtype flag (detected on device)

__device__ __forceinline__ float lrelu(float v) { return v >= 0.f ? v : 0.2f * v; }

// ---------------- dtype detection: int64 edge data has all-small values ----------------
__global__ void k_detect(const void* __restrict__ ei) {
  if (threadIdx.x == 0) {
    const long long* p = (const long long*)ei;
    int ok = 1;
    for (int i = 0; i < 64; i++) {
      long long v = p[i];
      if (v < 0 || v >= NN) { ok = 0; break; }
    }
    g_is64 = ok;
  }
}

// ---------------- setup: edge conversion + CSR build ----------------
__global__ void k_zero() {
  int i = blockIdx.x * 256 + threadIdx.x;
  if (i < NN) { g_deg[i] = 0; g_cur[i] = 0; }
  if (i < 256) { g_stats1[i] = 0.f; g_stats2[i] = 0.f; }
}

__global__ void k_edges(const void* __restrict__ ei) {
  int i = blockIdx.x * 256 + threadIdx.x;
  if (i < NE) {
    int s, d;
    if (g_is64) {
      const long long* p = (const long long*)ei;
      s = (int)p[i];
      d = (int)p[NE + i];
    } else {
      const int* p = (const int*)ei;
      s = p[i];
      d = p[NE + i];
    }
    // crash-guard: keep any surprise in-bounds (degrades to rel_err signal)
    if ((unsigned)s >= NN) s = 0;
    if ((unsigned)d >= NN) d = 0;
    g_src[i] = s;
    g_dst[i] = d;
    atomicAdd(&g_deg[d], 1);
  }
}

__global__ void k_scan_a() {
  int i = blockIdx.x * 1024 + threadIdx.x;
  int v = (i < NN) ? g_deg[i] : 0;
#pragma unroll
  for (int o = 16; o; o >>= 1) v += __shfl_xor_sync(0xffffffffu, v, o);
  __shared__ int sb[32];
  if ((threadIdx.x & 31) == 0) sb[threadIdx.x >> 5] = v;
  __syncthreads();
  if (threadIdx.x == 0) {
    int t = 0;
#pragma unroll
    for (int w = 0; w < 32; w++) t += sb[w];
    g_bsum[blockIdx.x] = t;
  }
}

__global__ void k_scan_b() {
  int acc = 0;
  for (int b = 0; b < NB; b++) { g_boff[b] = acc; acc += g_bsum[b]; }
}

__global__ void k_scan_c() {
  int t = threadIdx.x;
  int i = blockIdx.x * 1024 + t;
  int v = (i < NN) ? g_deg[i] : 0;
  __shared__ int sb[1024];
  sb[t] = v;
  __syncthreads();
  for (int o = 1; o < 1024; o <<= 1) {
    int x = (t >= o) ? sb[t - o] : 0;
    __syncthreads();
    sb[t] += x;
    __syncthreads();
  }
  if (i < NN) g_rs[i] = g_boff[blockIdx.x] + sb[t] - v;  // exclusive
  if (i == 0) g_rs[NN] = NE;
}

__global__ void k_scatter() {
  int i = blockIdx.x * 256 + threadIdx.x;
  if (i < NE) {
    int d = g_dst[i];
    int p = atomicAdd(&g_cur[d], 1);
    g_eid[g_rs[d] + p] = i;
  }
}

// ---------------- GEMM: out[N,128] = A[N,K] @ W[K,128] (+bias)(+addC)(leaky)(stats) ----------------
constexpr int M_BNA = 1, M_LEAKY = 2, M_ADDC = 4, M_STATS = 8, M_BIAS = 16;

#define GFMA(av, wv)                               \
  acc[r].x = fmaf((av), (wv).x, acc[r].x);         \
  acc[r].y = fmaf((av), (wv).y, acc[r].y);         \
  acc[r].z = fmaf((av), (wv).z, acc[r].z);         \
  acc[r].w = fmaf((av), (wv).w, acc[r].w);

// SEL: 0 -> A=Ap,    out=g_h1,  stats1
//      1 -> A=g_h1,  out=g_t1   (BN affine on A)
//      2 -> A=g_skip,out=g_t2
//      3 -> A=g_skip,out=outp,  stats2, addC=g_out2
template <int K, int MODE, int SEL>
__global__ __launch_bounds__(256) void k_gemm(const float* __restrict__ Ap,
                                              const float* __restrict__ W,
                                              const float* __restrict__ bias,
                                              float* __restrict__ outp) {
  const float* A   = (SEL == 0) ? Ap : (SEL == 1) ? g_h1 : g_skip;
  float* out       = (SEL == 0) ? g_h1 : (SEL == 1) ? g_t1 : (SEL == 2) ? g_t2 : outp;
  float* stats     = (SEL == 0) ? g_stats1 : g_stats2;

  __shared__ float As[64][64];
  __shared__ float Ws[64][128];

  int tid = threadIdx.x;
  int tx = tid & 31, ty = tid >> 5;     // thread tile: 8 rows (ty*8) x 4 cols (tx*4)
  int row0 = blockIdx.x * 64;

  float4 acc[8];
#pragma unroll
  for (int r = 0; r < 8; r++) acc[r] = make_float4(0.f, 0.f, 0.f, 0.f);

  for (int kc = 0; kc < K; kc += 64) {
#pragma unroll
    for (int i = 0; i < 4; i++) {
      int idx = tid * 4 + i * 1024;   // 0..4095
      int r = idx >> 6, k = idx & 63;
      int grow = row0 + r;
      float4 v = make_float4(0.f, 0.f, 0.f, 0.f);
      if (grow < NN) v = *(const float4*)(A + (size_t)grow * K + kc + k);
      if (MODE & M_BNA) {
        int kg = kc + k;
        v.x = fmaf(v.x, g_sc1[kg],     g_sh1[kg]);
        v.y = fmaf(v.y, g_sc1[kg + 1], g_sh1[kg + 1]);
        v.z = fmaf(v.z, g_sc1[kg + 2], g_sh1[kg + 2]);
        v.w = fmaf(v.w, g_sc1[kg + 3], g_sh1[kg + 3]);
      }
      *(float4*)&As[r][k] = v;
    }
#pragma unroll
    for (int i = 0; i < 8; i++) {
      int idx = tid * 4 + i * 1024;   // 0..8191
      int k = idx >> 7, c = idx & 127;
      *(float4*)&Ws[k][c] = *(const float4*)(W + (size_t)(kc + k) * 128 + c);
    }
    __syncthreads();
#pragma unroll
    for (int kk = 0; kk < 64; kk += 4) {
      float4 wv0 = *(float4*)&Ws[kk][tx * 4];
      float4 wv1 = *(float4*)&Ws[kk + 1][tx * 4];
      float4 wv2 = *(float4*)&Ws[kk + 2][tx * 4];
      float4 wv3 = *(float4*)&Ws[kk + 3][tx * 4];
#pragma unroll
      for (int r = 0; r < 8; r++) {
        float4 a4 = *(float4*)&As[ty * 8 + r][kk];
        GFMA(a4.x, wv0)
        GFMA(a4.y, wv1)
        GFMA(a4.z, wv2)
        GFMA(a4.w, wv3)
      }
    }
    __syncthreads();
  }

  int col = tx * 4;
  float4 bv = make_float4(0.f, 0.f, 0.f, 0.f);
  if (MODE & M_BIAS) bv = *(const float4*)(bias + col);
  float4 p1 = make_float4(0.f, 0.f, 0.f, 0.f);
  float4 p2 = make_float4(0.f, 0.f, 0.f, 0.f);
#pragma unroll
  for (int r = 0; r < 8; r++) {
    int grow = row0 + ty * 8 + r;
    if (grow < NN) {
      float4 v = acc[r];
      if (MODE & M_BIAS) { v.x += bv.x; v.y += bv.y; v.z += bv.z; v.w += bv.w; }
      if (MODE & M_ADDC) {
        float4 cv = *(const float4*)(g_out2 + (size_t)grow * 128 + col);
        v.x += cv.x; v.y += cv.y; v.z += cv.z; v.w += cv.w;
      }
      if (MODE & M_LEAKY) { v.x = lrelu(v.x); v.y = lrelu(v.y); v.z = lrelu(v.z); v.w = lrelu(v.w); }
      *(float4*)(out + (size_t)grow * 128 + col) = v;
      if (MODE & M_STATS) {
        p1.x += v.x; p1.y += v.y; p1.z += v.z; p1.w += v.w;
        p2.x += v.x * v.x; p2.y += v.y * v.y; p2.z += v.z * v.z; p2.w += v.w * v.w;
      }
    }
  }
  if (MODE & M_STATS) {
    __syncthreads();
    float* red = &As[0][0];   // reuse smem: 2048 floats needed, 4096 available
    red[ty * 128 + col]     = p1.x;  red[ty * 128 + col + 1] = p1.y;
    red[ty * 128 + col + 2] = p1.z;  red[ty * 128 + col + 3] = p1.w;
    red[1024 + ty * 128 + col]     = p2.x;  red[1024 + ty * 128 + col + 1] = p2.y;
    red[1024 + ty * 128 + col + 2] = p2.z;  red[1024 + ty * 128 + col + 3] = p2.w;
    __syncthreads();
    if (tid < 128) {
      float s1 = 0.f, s2 = 0.f;
#pragma unroll
      for (int w = 0; w < 8; w++) { s1 += red[w * 128 + tid]; s2 += red[1024 + w * 128 + tid]; }
      atomicAdd(&stats[tid], s1);
      atomicAdd(&stats[128 + tid], s2);
    }
  }
}

// ---------------- BN finalize: scale/shift from colsum/colsumsq ----------------
template <int L>
__global__ void k_bnfin(const float* __restrict__ gamma, const float* __restrict__ beta) {
  int i = threadIdx.x;
  const float* st = (L == 1) ? g_stats1 : g_stats2;
  float mean = st[i] * (1.f / NN);
  float var = st[128 + i] * (1.f / NN) - mean * mean;
  float sc = rsqrtf(var + 1e-5f) * gamma[i];
  float sh = beta[i] - mean * sc;
  if (L == 1) { g_sc1[i] = sc; g_sh1[i] = sh; }
  else        { g_sc2[i] = sc; g_sh2[i] = sh; }
}

// ---------------- attention per-node dot products ----------------
template <int H>
__global__ __launch_bounds__(256) void k_att(const float* __restrict__ avs,
                                             const float* __restrict__ avd) {
  int tid = threadIdx.x;
  int node = blockIdx.x * 2 + (tid >> 7);
  int j = tid & 127;
  const float* t = (H == 8) ? g_t1 : g_t2;
  float tv = t[(size_t)node * 128 + j];
  float ps = tv * avs[j];
  float pd = tv * avd[j];
#pragma unroll
  for (int o = 8; o; o >>= 1) {
    ps += __shfl_xor_sync(0xffffffffu, ps, o);
    pd += __shfl_xor_sync(0xffffffffu, pd, o);
  }
  if (H == 8) {
    if ((j & 15) == 0) {
      g_as1[node * 8 + (j >> 4)] = ps;
      g_ad1[node * 8 + (j >> 4)] = pd;
    }
  } else {
    __shared__ float sb[2][8][2];
    if ((j & 15) == 0) { sb[tid >> 7][j >> 4][0] = ps; sb[tid >> 7][j >> 4][1] = pd; }
    __syncthreads();
    if (j == 0) {
      float a = 0.f, b = 0.f;
#pragma unroll
      for (int s = 0; s < 8; s++) { a += sb[tid >> 7][s][0]; b += sb[tid >> 7][s][1]; }
      g_as2[node] = a;
      g_ad2[node] = b;
    }
  }
}

template <int H>
__device__ __forceinline__ void load_as(float* dst, const float* __restrict__ p, int s) {
  if constexpr (H == 8) {
    float4 a = __ldg((const float4*)(p + (size_t)s * 8));
    float4 b = __ldg((const float4*)(p + (size_t)s * 8 + 4));
    dst[0] = a.x; dst[1] = a.y; dst[2] = a.z; dst[3] = a.w;
    dst[4] = b.x; dst[5] = b.y; dst[6] = b.z; dst[7] = b.w;
  } else {
    dst[0] = __ldg(p + s);
  }
}

// ---------------- GAT aggregation: one block (128 thr) per dst node ----------------
template <int H, bool LK>
__global__ __launch_bounds__(128) void k_gat(const float* __restrict__ bias) {
  const float* t   = (H == 8) ? g_t1  : g_t2;
  const float* asv = (H == 8) ? g_as1 : g_as2;
  const float* adv = (H == 8) ? g_ad1 : g_ad2;
  float* out       = (H == 8) ? g_skip : g_out2;

  int node = blockIdx.x, tid = threadIdx.x;
  int beg = g_rs[node];
  int cnt = g_rs[node + 1] - beg;
  int lane = tid & 31, warp = tid >> 5;

  float ad[H];
  load_as<H>(ad, adv, node);

  __shared__ float sred[4][8];

  // phase 1: per-head max over in-edges
  float mx[H];
#pragma unroll
  for (int h = 0; h < H; h++) mx[h] = -1e30f;
  for (int i = tid; i < cnt; i += 128) {
    int s = __ldg(&g_src[__ldg(&g_eid[beg + i])]);
    float av[H];
    load_as<H>(av, asv, s);
#pragma unroll
    for (int h = 0; h < H; h++) mx[h] = fmaxf(mx[h], lrelu(av[h] + ad[h]));
  }
#pragma unroll
  for (int h = 0; h < H; h++)
#pragma unroll
    for (int o = 16; o; o >>= 1) mx[h] = fmaxf(mx[h], __shfl_xor_sync(0xffffffffu, mx[h], o));
  if (lane == 0) {
#pragma unroll
    for (int h = 0; h < H; h++) sred[warp][h] = mx[h];
  }
  __syncthreads();
#pragma unroll
  for (int h = 0; h < H; h++)
    mx[h] = fmaxf(fmaxf(sred[0][h], sred[1][h]), fmaxf(sred[2][h], sred[3][h]));
  __syncthreads();

  // phase 2: softmax denominator
  float dn[H];
#pragma unroll
  for (int h = 0; h < H; h++) dn[h] = 0.f;
  for (int i = tid; i < cnt; i += 128) {
    int s = __ldg(&g_src[__ldg(&g_eid[beg + i])]);
    float av[H];
    load_as<H>(av, asv, s);
#pragma unroll
    for (int h = 0; h < H; h++) dn[h] += __expf(lrelu(av[h] + ad[h]) - mx[h]);
  }
#pragma unroll
  for (int h = 0; h < H; h++)
#pragma unroll
    for (int o = 16; o; o >>= 1) dn[h] += __shfl_xor_sync(0xffffffffu, dn[h], o);
  if (lane == 0) {
#pragma unroll
    for (int h = 0; h < H; h++) sred[warp][h] = dn[h];
  }
  __syncthreads();
  float inv[H];
#pragma unroll
  for (int h = 0; h < H; h++)
    inv[h] = 1.f / fmaxf(sred[0][h] + sred[1][h] + sred[2][h] + sred[3][h], 1e-16f);
  __syncthreads();

  // phase 3: weighted gather-accumulate (thread = feature channel)
  constexpr int CH = 128 / H;  // edges per chunk
  __shared__ int   ssrc[CH];
  __shared__ float salpha[128];
  int myh = (H == 8) ? (tid >> 4) : 0;
  float acc = 0.f;
  for (int base = 0; base < cnt; base += CH) {
    int c = min(CH, cnt - base);
    int el = tid / H, h = tid % H;
    if (el < c) {
      int s = __ldg(&g_src[__ldg(&g_eid[beg + base + el])]);
      if (h == 0) ssrc[el] = s;
      float av = (H == 8) ? __ldg(&asv[(size_t)s * 8 + h]) : __ldg(&asv[s]);
      salpha[el * H + h] = __expf(lrelu(av + ad[h]) - mx[h]) * inv[h];
    }
    __syncthreads();
    for (int e2 = 0; e2 < c; e2++)
      acc = fmaf(salpha[e2 * H + myh], __ldg(&t[(size_t)ssrc[e2] * 128 + tid]), acc);
    __syncthreads();
  }

  float v = acc + bias[tid];
  if (LK) v = lrelu(v);
  out[(size_t)node * 128 + tid] = v;
}

// ---------------- final: BN2 affine + L2 row normalize (in-place on d_out) ----------------
__global__ __launch_bounds__(128) void k_final(float* __restrict__ out) {
  int node = blockIdx.x, tid = threadIdx.x;
  float v = out[(size_t)node * 128 + tid] * g_sc2[tid] + g_sh2[tid];
  float q = v * v;
#pragma unroll
  for (int o = 16; o; o >>= 1) q += __shfl_xor_sync(0xffffffffu, q, o);
  __shared__ float sq[4];
  if ((tid & 31) == 0) sq[tid >> 5] = q;
  __syncthreads();
  float tot = sq[0] + sq[1] + sq[2] + sq[3];
  float r = 1.f / fmaxf(sqrtf(tot), 1e-12f);
  out[(size_t)node * 128 + tid] = v * r;
}

}  // namespace

extern "C" void kernel_launch(void* const* d_in, const int* in_sizes, int n_in,
                              void* d_out, int out_size) {
  const float* x        = (const float*)d_in[0];
  const float* W_in     = (const float*)d_in[1];
  const float* b_in     = (const float*)d_in[2];
  const float* gamma1   = (const float*)d_in[3];
  const float* beta1    = (const float*)d_in[4];
  const float* W1       = (const float*)d_in[5];
  const float* att_src1 = (const float*)d_in[6];
  const float* att_dst1 = (const float*)d_in[7];
  const float* bias1    = (const float*)d_in[8];
  const float* W2       = (const float*)d_in[9];
  const float* att_src2 = (const float*)d_in[10];
  const float* att_dst2 = (const float*)d_in[11];
  const float* bias2    = (const float*)d_in[12];
  const float* W_skip   = (const float*)d_in[13];
  const float* b_skip   = (const float*)d_in[14];
  const float* gamma2   = (const float*)d_in[15];
  const float* beta2    = (const float*)d_in[16];
  const void*  eidx     = d_in[17];
  float* out = (float*)d_out;

  // CSR build
  k_detect<<<1, 32>>>(eidx);
  k_zero<<<(NN + 255) / 256, 256>>>();
  k_edges<<<(NE + 255) / 256, 256>>>(eidx);
  k_scan_a<<<NB, 1024>>>();
  k_scan_b<<<1, 1>>>();
  k_scan_c<<<NB, 1024>>>();
  k_scatter<<<(NE + 255) / 256, 256>>>();

  const int GB = (NN + 63) / 64;
  // h1 = leaky(x @ W_in + b_in), BN1 stats
  k_gemm<KIN, M_BIAS | M_LEAKY | M_STATS, 0><<<GB, 256>>>(x, W_in, b_in, nullptr);
  k_bnfin<1><<<1, 128>>>(gamma1, beta1);
  // t1 = BN1(h1) @ W1
  k_gemm<128, M_BNA, 1><<<GB, 256>>>(nullptr, W1, nullptr, nullptr);
  // attention logits layer 1
  k_att<8><<<NN / 2, 256>>>(att_src1, att_dst1);
  // skip = leaky(gat1 + bias1)
  k_gat<8, true><<<NN, 128>>>(bias1);
  // t2 = skip @ W2
  k_gemm<128, 0, 2><<<GB, 256>>>(nullptr, W2, nullptr, nullptr);
  // attention logits layer 2
  k_att<1><<<NN / 2, 256>>>(att_src2, att_dst2);
  // out2 = gat2 + bias2
  k_gat<1, false><<<NN, 128>>>(bias2);
  // pre = skip @ W_skip + b_skip + out2, BN2 stats  (written to d_out)
  k_gemm<128, M_BIAS | M_ADDC | M_STATS, 3><<<GB, 256>>>(nullptr, W_skip, b_skip, out);
  k_bnfin<2><<<1, 128>>>(gamma2, beta2);
  // BN2 affine + L2 normalize, in place
  k_final<<<NN, 128>>>(out);
}

// round 5
// speedup vs baseline: 1.0838x; 1.0838x over previous
#include <cuda_runtime.h>

namespace {

constexpr int NN  = 50000;   // nodes
constexpr int NE  = 800000;  // edges
constexpr int KIN = 256;     // in_dim
constexpr int NB  = (NN + 1023) / 1024;  // scan blocks = 49

// ---------------- scratch (static device memory; no allocations) ----------------
__device__ float g_h1[NN * 128];     // leaky(x@W_in+b_in)  (pre-BN1)
__device__ float g_t1[NN * 128];     // BN1(h1) @ W1
__device__ float g_skip[NN * 128];   // leaky(gat1 + bias1)
__device__ float g_t2[NN * 128];     // skip @ W2
__device__ float g_out2[NN * 128];   // gat2 + bias2
__device__ float g_as1[NN * 8];
__device__ float g_ad1[NN * 8];
__device__ float g_as2[NN];
__device__ float g_ad2[NN];
__device__ int   g_src[NE];
__device__ int   g_dst[NE];
__device__ int   g_eid[NE];          // edge ids sorted by dst (CSR)
__device__ int   g_deg[NN];
__device__ int   g_cur[NN];
__device__ int   g_rs[NN + 1];       // CSR row starts
__device__ int   g_bsum[NB];
__device__ int   g_boff[NB];
__device__ float g_stats1[256];      // [0:128) colsum, [128:256) colsumsq
__device__ float g_stats2[256];
__device__ float g_sc1[128], g_sh1[128], g_sc2[128], g_sh2[128];
__device__ int   g_is64;             // edge_index dtype flag (detected on device)

__device__ __forceinline__ float lrelu(float v) { return v >= 0.f ? v : 0.2f * v; }

__device__ __forceinline__ unsigned f2tf32(float f) {
  unsigned u;
  asm("cvt.rna.tf32.f32 %0, %1;" : "=r"(u) : "f"(f));
  return u;
}

// ---------------- dtype detection: int64 edge data has all-small values ----------------
__global__ void k_detect(const void* __restrict__ ei) {
  if (threadIdx.x == 0) {
    const long long* p = (const long long*)ei;
    int ok = 1;
    for (int i = 0; i < 64; i++) {
      long long v = p[i];
      if (v < 0 || v >= NN) { ok = 0; break; }
    }
    g_is64 = ok;
  }
}

// ---------------- setup: edge conversion + CSR build ----------------
__global__ void k_zero() {
  int i = blockIdx.x * 256 + threadIdx.x;
  if (i < NN) { g_deg[i] = 0; g_cur[i] = 0; }
  if (i < 256) { g_stats1[i] = 0.f; g_stats2[i] = 0.f; }
}

__global__ void k_edges(const void* __restrict__ ei) {
  int i = blockIdx.x * 256 + threadIdx.x;
  if (i < NE) {
    int s, d;
    if (g_is64) {
      const long long* p = (const long long*)ei;
      s = (int)p[i];
      d = (int)p[NE + i];
    } else {
      const int* p = (const int*)ei;
      s = p[i];
      d = p[NE + i];
    }
    if ((unsigned)s >= NN) s = 0;
    if ((unsigned)d >= NN) d = 0;
    g_src[i] = s;
    g_dst[i] = d;
    atomicAdd(&g_deg[d], 1);
  }
}

__global__ void k_scan_a() {
  int i = blockIdx.x * 1024 + threadIdx.x;
  int v = (i < NN) ? g_deg[i] : 0;
#pragma unroll
  for (int o = 16; o; o >>= 1) v += __shfl_xor_sync(0xffffffffu, v, o);
  __shared__ int sb[32];
  if ((threadIdx.x & 31) == 0) sb[threadIdx.x >> 5] = v;
  __syncthreads();
  if (threadIdx.x == 0) {
    int t = 0;
#pragma unroll
    for (int w = 0; w < 32; w++) t += sb[w];
    g_bsum[blockIdx.x] = t;
  }
}

__global__ void k_scan_b() {
  int acc = 0;
  for (int b = 0; b < NB; b++) { g_boff[b] = acc; acc += g_bsum[b]; }
}

__global__ void k_scan_c() {
  int t = threadIdx.x;
  int i = blockIdx.x * 1024 + t;
  int v = (i < NN) ? g_deg[i] : 0;
  __shared__ int sb[1024];
  sb[t] = v;
  __syncthreads();
  for (int o = 1; o < 1024; o <<= 1) {
    int x = (t >= o) ? sb[t - o] : 0;
    __syncthreads();
    sb[t] += x;
    __syncthreads();
  }
  if (i < NN) g_rs[i] = g_boff[blockIdx.x] + sb[t] - v;  // exclusive
  if (i == 0) g_rs[NN] = NE;
}

__global__ void k_scatter() {
  int i = blockIdx.x * 256 + threadIdx.x;
  if (i < NE) {
    int d = g_dst[i];
    int p = atomicAdd(&g_cur[d], 1);
    g_eid[g_rs[d] + p] = i;
  }
}

// ---------------- TF32 tensor-core GEMM: out[N,128] = A[N,K] @ W[K,128] ----------------
constexpr int M_BNA = 1, M_LEAKY = 2, M_ADDC = 4, M_BIAS = 16;

__device__ __forceinline__ void mma_tf32(float4& c, const unsigned a[4], const unsigned b[2]) {
  asm volatile(
      "mma.sync.aligned.m16n8k8.row.col.f32.tf32.tf32.f32 "
      "{%0,%1,%2,%3}, {%4,%5,%6,%7}, {%8,%9}, {%0,%1,%2,%3};"
      : "+f"(c.x), "+f"(c.y), "+f"(c.z), "+f"(c.w)
      : "r"(a[0]), "r"(a[1]), "r"(a[2]), "r"(a[3]), "r"(b[0]), "r"(b[1]));
}

// SEL: 0 -> A=Ap,    out=g_h1   (bias b_in, leaky)
//      1 -> A=g_h1,  out=g_t1   (BN1 affine on A)
//      2 -> A=g_skip,out=g_t2
//      3 -> A=g_skip,out=outp   (bias b_skip, addC=g_out2)
template <int K, int MODE, int SEL>
__global__ __launch_bounds__(256, 2) void k_gemm_tc(const float* __restrict__ Ap,
                                                    const float* __restrict__ W,
                                                    const float* __restrict__ bias,
                                                    float* __restrict__ outp) {
  const float* A = (SEL == 0) ? Ap : (SEL == 1) ? g_h1 : g_skip;
  float* out     = (SEL == 0) ? g_h1 : (SEL == 1) ? g_t1 : (SEL == 2) ? g_t2 : outp;

  // conflict-free by construction: As stride 36 (4r+c banks), Ws stride 136 (8k+n banks)
  __shared__ unsigned As[128 * 36];
  __shared__ unsigned Ws[32 * 136];

  int tid = threadIdx.x;
  int lane = tid & 31, wid = tid >> 5;
  int gr = lane >> 2, gc = lane & 3;     // mma group row / col-in-group
  int warp_m = wid & 3, warp_n = wid >> 2;
  int row0 = blockIdx.x * 128;

  float4 acc[2][8];
#pragma unroll
  for (int mt = 0; mt < 2; mt++)
#pragma unroll
    for (int nt = 0; nt < 8; nt++) acc[mt][nt] = make_float4(0.f, 0.f, 0.f, 0.f);

  for (int kc = 0; kc < K; kc += 32) {
    // load A tile: 128 rows x 32 k  (4 float4 per thread)
#pragma unroll
    for (int i = 0; i < 4; i++) {
      int idx = tid * 4 + i * 1024;     // 0..4095
      int r = idx >> 5, c = idx & 31;
      int grow = row0 + r;
      float4 v = make_float4(0.f, 0.f, 0.f, 0.f);
      if (grow < NN) v = *(const float4*)(A + (size_t)grow * K + kc + c);
      if (MODE & M_BNA) {
        int kg = kc + c;
        v.x = fmaf(v.x, g_sc1[kg],     g_sh1[kg]);
        v.y = fmaf(v.y, g_sc1[kg + 1], g_sh1[kg + 1]);
        v.z = fmaf(v.z, g_sc1[kg + 2], g_sh1[kg + 2]);
        v.w = fmaf(v.w, g_sc1[kg + 3], g_sh1[kg + 3]);
      }
      unsigned* p = &As[r * 36 + c];
      p[0] = f2tf32(v.x); p[1] = f2tf32(v.y); p[2] = f2tf32(v.z); p[3] = f2tf32(v.w);
    }
    // load W tile: 32 k x 128 n  (4 float4 per thread)
#pragma unroll
    for (int i = 0; i < 4; i++) {
      int idx = tid * 4 + i * 1024;     // 0..4095
      int k = idx >> 7, n = idx & 127;
      float4 v = *(const float4*)(W + (size_t)(kc + k) * 128 + n);
      unsigned* p = &Ws[k * 136 + n];
      p[0] = f2tf32(v.x); p[1] = f2tf32(v.y); p[2] = f2tf32(v.z); p[3] = f2tf32(v.w);
    }
    __syncthreads();

#pragma unroll
    for (int kk = 0; kk < 32; kk += 8) {
      unsigned a[2][4];
#pragma unroll
      for (int mt = 0; mt < 2; mt++) {
        int rb = warp_m * 32 + mt * 16;
        a[mt][0] = As[(rb + gr)     * 36 + kk + gc];
        a[mt][1] = As[(rb + gr + 8) * 36 + kk + gc];
        a[mt][2] = As[(rb + gr)     * 36 + kk + gc + 4];
        a[mt][3] = As[(rb + gr + 8) * 36 + kk + gc + 4];
      }
      unsigned b[8][2];
#pragma unroll
      for (int nt = 0; nt < 8; nt++) {
        int n = warp_n * 64 + nt * 8 + gr;
        b[nt][0] = Ws[(kk + gc)     * 136 + n];
        b[nt][1] = Ws[(kk + gc + 4) * 136 + n];
      }
#pragma unroll
      for (int mt = 0; mt < 2; mt++)
#pragma unroll
        for (int nt = 0; nt < 8; nt++) mma_tf32(acc[mt][nt], a[mt], b[nt]);
    }
    __syncthreads();
  }

  // epilogue: c0,c1 at (r, col..col+1), c2,c3 at (r+8, ...)
#pragma unroll
  for (int nt = 0; nt < 8; nt++) {
    int col = warp_n * 64 + nt * 8 + gc * 2;
    float2 bv = make_float2(0.f, 0.f);
    if (MODE & M_BIAS) bv = *(const float2*)(bias + col);
#pragma unroll
    for (int mt = 0; mt < 2; mt++) {
      int r0 = row0 + warp_m * 32 + mt * 16 + gr;
#pragma unroll
      for (int hh = 0; hh < 2; hh++) {
        int r = r0 + hh * 8;
        if (r < NN) {
          float2 v = hh ? make_float2(acc[mt][nt].z, acc[mt][nt].w)
                        : make_float2(acc[mt][nt].x, acc[mt][nt].y);
          if (MODE & M_BIAS) { v.x += bv.x; v.y += bv.y; }
          if (MODE & M_ADDC) {
            float2 cv = *(const float2*)(g_out2 + (size_t)r * 128 + col);
            v.x += cv.x; v.y += cv.y;
          }
          if (MODE & M_LEAKY) { v.x = lrelu(v.x); v.y = lrelu(v.y); }
          *(float2*)(out + (size_t)r * 128 + col) = v;
        }
      }
    }
  }
}

// ---------------- column stats (sum, sumsq) for BN ----------------
// L=1 reads g_h1 (device symbol resolved IN DEVICE CODE); L=2 reads the param.
template <int L>
__global__ __launch_bounds__(256) void k_colstats(const float* __restrict__ srcp) {
  const float* src = (L == 1) ? g_h1 : srcp;
  int col = threadIdx.x & 127;
  int half = threadIdx.x >> 7;
  float s = 0.f, q = 0.f;
  for (int i = 0; i < 256; i++) {
    int r = blockIdx.x * 512 + i * 2 + half;
    if (r < NN) {
      float v = src[(size_t)r * 128 + col];
      s += v;
      q += v * v;
    }
  }
  __shared__ float red[512];
  red[threadIdx.x] = s;
  red[256 + threadIdx.x] = q;
  __syncthreads();
  float* stats = (L == 1) ? g_stats1 : g_stats2;
  if (threadIdx.x < 128) {
    atomicAdd(&stats[threadIdx.x], red[threadIdx.x] + red[threadIdx.x + 128]);
    atomicAdd(&stats[128 + threadIdx.x], red[256 + threadIdx.x] + red[384 + threadIdx.x]);
  }
}

// ---------------- BN finalize: scale/shift from colsum/colsumsq ----------------
template <int L>
__global__ void k_bnfin(const float* __restrict__ gamma, const float* __restrict__ beta) {
  int i = threadIdx.x;
  const float* st = (L == 1) ? g_stats1 : g_stats2;
  float mean = st[i] * (1.f / NN);
  float var = st[128 + i] * (1.f / NN) - mean * mean;
  float sc = rsqrtf(var + 1e-5f) * gamma[i];
  float sh = beta[i] - mean * sc;
  if (L == 1) { g_sc1[i] = sc; g_sh1[i] = sh; }
  else        { g_sc2[i] = sc; g_sh2[i] = sh; }
}

// ---------------- attention per-node dot products ----------------
template <int H>
__global__ __launch_bounds__(256) void k_att(const float* __restrict__ avs,
                                             const float* __restrict__ avd) {
  int tid = threadIdx.x;
  int node = blockIdx.x * 2 + (tid >> 7);
  int j = tid & 127;
  const float* t = (H == 8) ? g_t1 : g_t2;
  float tv = t[(size_t)node * 128 + j];
  float ps = tv * avs[j];
  float pd = tv * avd[j];
#pragma unroll
  for (int o = 8; o; o >>= 1) {
    ps += __shfl_xor_sync(0xffffffffu, ps, o);
    pd += __shfl_xor_sync(0xffffffffu, pd, o);
  }
  if (H == 8) {
    if ((j & 15) == 0) {
      g_as1[node * 8 + (j >> 4)] = ps;
      g_ad1[node * 8 + (j >> 4)] = pd;
    }
  } else {
    __shared__ float sb[2][8][2];
    if ((j & 15) == 0) { sb[tid >> 7][j >> 4][0] = ps; sb[tid >> 7][j >> 4][1] = pd; }
    __syncthreads();
    if (j == 0) {
      float a = 0.f, b = 0.f;
#pragma unroll
      for (int s = 0; s < 8; s++) { a += sb[tid >> 7][s][0]; b += sb[tid >> 7][s][1]; }
      g_as2[node] = a;
      g_ad2[node] = b;
    }
  }
}

template <int H>
__device__ __forceinline__ void load_as(float* dst, const float* __restrict__ p, int s) {
  if constexpr (H == 8) {
    float4 a = __ldg((const float4*)(p + (size_t)s * 8));
    float4 b = __ldg((const float4*)(p + (size_t)s * 8 + 4));
    dst[0] = a.x; dst[1] = a.y; dst[2] = a.z; dst[3] = a.w;
    dst[4] = b.x; dst[5] = b.y; dst[6] = b.z; dst[7] = b.w;
  } else {
    dst[0] = __ldg(p + s);
  }
}

// ---------------- GAT aggregation: one block (128 thr) per dst node ----------------
template <int H, bool LK>
__global__ __launch_bounds__(128) void k_gat(const float* __restrict__ bias) {
  const float* t   = (H == 8) ? g_t1  : g_t2;
  const float* asv = (H == 8) ? g_as1 : g_as2;
  const float* adv = (H == 8) ? g_ad1 : g_ad2;
  float* out       = (H == 8) ? g_skip : g_out2;

  int node = blockIdx.x, tid = threadIdx.x;
  int beg = g_rs[node];
  int cnt = g_rs[node + 1] - beg;
  int lane = tid & 31, warp = tid >> 5;

  float ad[H];
  load_as<H>(ad, adv, node);

  __shared__ float sred[4][8];

  // phase 1: per-head max over in-edges
  float mx[H];
#pragma unroll
  for (int h = 0; h < H; h++) mx[h] = -1e30f;
  for (int i = tid; i < cnt; i += 128) {
    int s = __ldg(&g_src[__ldg(&g_eid[beg + i])]);
    float av[H];
    load_as<H>(av, asv, s);
#pragma unroll
    for (int h = 0; h < H; h++) mx[h] = fmaxf(mx[h], lrelu(av[h] + ad[h]));
  }
#pragma unroll
  for (int h = 0; h < H; h++)
#pragma unroll
    for (int o = 16; o; o >>= 1) mx[h] = fmaxf(mx[h], __shfl_xor_sync(0xffffffffu, mx[h], o));
  if (lane == 0) {
#pragma unroll
    for (int h = 0; h < H; h++) sred[warp][h] = mx[h];
  }
  __syncthreads();
#pragma unroll
  for (int h = 0; h < H; h++)
    mx[h] = fmaxf(fmaxf(sred[0][h], sred[1][h]), fmaxf(sred[2][h], sred[3][h]));
  __syncthreads();

  // phase 2: softmax denominator
  float dn[H];
#pragma unroll
  for (int h = 0; h < H; h++) dn[h] = 0.f;
  for (int i = tid; i < cnt; i += 128) {
    int s = __ldg(&g_src[__ldg(&g_eid[beg + i])]);
    float av[H];
    load_as<H>(av, asv, s);
#pragma unroll
    for (int h = 0; h < H; h++) dn[h] += __expf(lrelu(av[h] + ad[h]) - mx[h]);
  }
#pragma unroll
  for (int h = 0; h < H; h++)
#pragma unroll
    for (int o = 16; o; o >>= 1) dn[h] += __shfl_xor_sync(0xffffffffu, dn[h], o);
  if (lane == 0) {
#pragma unroll
    for (int h = 0; h < H; h++) sred[warp][h] = dn[h];
  }
  __syncthreads();
  float inv[H];
#pragma unroll
  for (int h = 0; h < H; h++)
    inv[h] = 1.f / fmaxf(sred[0][h] + sred[1][h] + sred[2][h] + sred[3][h], 1e-16f);
  __syncthreads();

  // phase 3: weighted gather-accumulate (thread = feature channel)
  constexpr int CH = 128 / H;  // edges per chunk
  __shared__ int   ssrc[CH];
  __shared__ float salpha[128];
  int myh = (H == 8) ? (tid >> 4) : 0;
  float acc = 0.f;
  for (int base = 0; base < cnt; base += CH) {
    int c = min(CH, cnt - base);
    int el = tid / H, h = tid % H;
    if (el < c) {
      int s = __ldg(&g_src[__ldg(&g_eid[beg + base + el])]);
      if (h == 0) ssrc[el] = s;
      float av = (H == 8) ? __ldg(&asv[(size_t)s * 8 + h]) : __ldg(&asv[s]);
      salpha[el * H + h] = __expf(lrelu(av + ad[h]) - mx[h]) * inv[h];
    }
    __syncthreads();
    for (int e2 = 0; e2 < c; e2++)
      acc = fmaf(salpha[e2 * H + myh], __ldg(&t[(size_t)ssrc[e2] * 128 + tid]), acc);
    __syncthreads();
  }

  float v = acc + bias[tid];
  if (LK) v = lrelu(v);
  out[(size_t)node * 128 + tid] = v;
}

// ---------------- final: BN2 affine + L2 row normalize (in-place on d_out) ----------------
__global__ __launch_bounds__(128) void k_final(float* __restrict__ out) {
  int node = blockIdx.x, tid = threadIdx.x;
  float v = out[(size_t)node * 128 + tid] * g_sc2[tid] + g_sh2[tid];
  float q = v * v;
#pragma unroll
  for (int o = 16; o; o >>= 1) q += __shfl_xor_sync(0xffffffffu, q, o);
  __shared__ float sq[4];
  if ((tid & 31) == 0) sq[tid >> 5] = q;
  __syncthreads();
  float tot = sq[0] + sq[1] + sq[2] + sq[3];
  float r = 1.f / fmaxf(sqrtf(tot), 1e-12f);
  out[(size_t)node * 128 + tid] = v * r;
}

}  // namespace

extern "C" void kernel_launch(void* const* d_in, const int* in_sizes, int n_in,
                              void* d_out, int out_size) {
  const float* x        = (const float*)d_in[0];
  const float* W_in     = (const float*)d_in[1];
  const float* b_in     = (const float*)d_in[2];
  const float* gamma1   = (const float*)d_in[3];
  const float* beta1    = (const float*)d_in[4];
  const float* W1       = (const float*)d_in[5];
  const float* att_src1 = (const float*)d_in[6];
  const float* att_dst1 = (const float*)d_in[7];
  const float* bias1    = (const float*)d_in[8];
  const float* W2       = (const float*)d_in[9];
  const float* att_src2 = (const float*)d_in[10];
  const float* att_dst2 = (const float*)d_in[11];
  const float* bias2    = (const float*)d_in[12];
  const float* W_skip   = (const float*)d_in[13];
  const float* b_skip   = (const float*)d_in[14];
  const float* gamma2   = (const float*)d_in[15];
  const float* beta2    = (const float*)d_in[16];
  const void*  eidx     = d_in[17];
  float* out = (float*)d_out;

  // CSR build
  k_detect<<<1, 32>>>(eidx);
  k_zero<<<(NN + 255) / 256, 256>>>();
  k_edges<<<(NE + 255) / 256, 256>>>(eidx);
  k_scan_a<<<NB, 1024>>>();
  k_scan_b<<<1, 1>>>();
  k_scan_c<<<NB, 1024>>>();
  k_scatter<<<(NE + 255) / 256, 256>>>();

  const int GB = (NN + 127) / 128;   // 391
  const int SB = (NN + 511) / 512;   // 98
  // h1 = leaky(x @ W_in + b_in), then BN1 stats (src resolved in device code)
  k_gemm_tc<KIN, M_BIAS | M_LEAKY, 0><<<GB, 256>>>(x, W_in, b_in, nullptr);
  k_colstats<1><<<SB, 256>>>(nullptr);
  k_bnfin<1><<<1, 128>>>(gamma1, beta1);
  // t1 = BN1(h1) @ W1
  k_gemm_tc<128, M_BNA, 1><<<GB, 256>>>(nullptr, W1, nullptr, nullptr);
  // attention logits layer 1
  k_att<8><<<NN / 2, 256>>>(att_src1, att_dst1);
  // skip = leaky(gat1 + bias1)
  k_gat<8, true><<<NN, 128>>>(bias1);
  // t2 = skip @ W2
  k_gemm_tc<128, 0, 2><<<GB, 256>>>(nullptr, W2, nullptr, nullptr);
  // attention logits layer 2
  k_att<1><<<NN / 2, 256>>>(att_src2, att_dst2);
  // out2 = gat2 + bias2
  k_gat<1, false><<<NN, 128>>>(bias2);
  // pre = skip @ W_skip + b_skip + out2  (written to d_out), then BN2 stats
  k_gemm_tc<128, M_BIAS | M_ADDC, 3><<<GB, 256>>>(nullptr, W_skip, b_skip, out);
  k_colstats<2><<<SB, 256>>>(out);
  k_bnfin<2><<<1, 128>>>(gamma2, beta2);
  // BN2 affine + L2 normalize, in place
  k_final<<<NN, 128>>>(out);
}

// round 6
// speedup vs baseline: 1.2368x; 1.1412x over previous
#include <cuda_runtime.h>

namespace {

constexpr int NN  = 50000;   // nodes
constexpr int NE  = 800000;  // edges
constexpr int KIN = 256;     // in_dim
constexpr int NB  = (NN + 1023) / 1024;  // scan blocks = 49

// ---------------- scratch (static device memory; no allocations) ----------------
__device__ float g_h1[NN * 128];     // leaky(x@W_in+b_in)  (pre-BN1)
__device__ float g_t1[NN * 128];     // BN1(h1) @ W1
__device__ float g_skip[NN * 128];   // leaky(gat1 + bias1)
__device__ float g_t2[NN * 128];     // skip @ W2
__device__ float g_out2[NN * 128];   // gat2 + bias2
__device__ float g_as1[NN * 8];
__device__ float g_ad1[NN * 8];
__device__ float g_as2[NN];
__device__ float g_ad2[NN];
__device__ int   g_src[NE];
__device__ int   g_dst[NE];
__device__ int   g_sby[NE];          // src ids sorted by dst (CSR order)
__device__ int   g_deg[NN];
__device__ int   g_cur[NN];
__device__ int   g_rs[NN + 1];       // CSR row starts
__device__ int   g_bsum[NB];
__device__ int   g_boff[NB];
__device__ float g_stats1[256];      // [0:128) colsum, [128:256) colsumsq
__device__ float g_stats2[256];
__device__ float g_sc1[128], g_sh1[128], g_sc2[128], g_sh2[128];
__device__ int   g_is64;             // edge_index dtype flag (detected on device)

__device__ __forceinline__ float lrelu(float v) { return v >= 0.f ? v : 0.2f * v; }

__device__ __forceinline__ unsigned f2tf32(float f) {
  unsigned u;
  asm("cvt.rna.tf32.f32 %0, %1;" : "=r"(u) : "f"(f));
  return u;
}

// ---------------- setup: zero + dtype detect ----------------
__global__ void k_zero(const void* __restrict__ ei) {
  int i = blockIdx.x * 256 + threadIdx.x;
  if (i < NN) { g_deg[i] = 0; g_cur[i] = 0; }
  if (i < 256) { g_stats1[i] = 0.f; g_stats2[i] = 0.f; }
  if (blockIdx.x == 0 && threadIdx.x == 0) {
    const long long* p = (const long long*)ei;
    int ok = 1;
    for (int j = 0; j < 64; j++) {
      long long v = p[j];
      if (v < 0 || v >= NN) { ok = 0; break; }
    }
    g_is64 = ok;
  }
}

__global__ void k_edges(const void* __restrict__ ei) {
  int i = blockIdx.x * 256 + threadIdx.x;
  if (i < NE) {
    int s, d;
    if (g_is64) {
      const long long* p = (const long long*)ei;
      s = (int)p[i];
      d = (int)p[NE + i];
    } else {
      const int* p = (const int*)ei;
      s = p[i];
      d = p[NE + i];
    }
    if ((unsigned)s >= NN) s = 0;
    if ((unsigned)d >= NN) d = 0;
    g_src[i] = s;
    g_dst[i] = d;
    atomicAdd(&g_deg[d], 1);
  }
}

__global__ void k_scan_a() {
  int i = blockIdx.x * 1024 + threadIdx.x;
  int v = (i < NN) ? g_deg[i] : 0;
#pragma unroll
  for (int o = 16; o; o >>= 1) v += __shfl_xor_sync(0xffffffffu, v, o);
  __shared__ int sb[32];
  if ((threadIdx.x & 31) == 0) sb[threadIdx.x >> 5] = v;
  __syncthreads();
  if (threadIdx.x == 0) {
    int t = 0;
#pragma unroll
    for (int w = 0; w < 32; w++) t += sb[w];
    g_bsum[blockIdx.x] = t;
  }
}

__global__ void k_scan_b() {
  int acc = 0;
  for (int b = 0; b < NB; b++) { g_boff[b] = acc; acc += g_bsum[b]; }
}

__global__ void k_scan_c() {
  int t = threadIdx.x;
  int i = blockIdx.x * 1024 + t;
  int v = (i < NN) ? g_deg[i] : 0;
  __shared__ int sb[1024];
  sb[t] = v;
  __syncthreads();
  for (int o = 1; o < 1024; o <<= 1) {
    int x = (t >= o) ? sb[t - o] : 0;
    __syncthreads();
    sb[t] += x;
    __syncthreads();
  }
  if (i < NN) g_rs[i] = g_boff[blockIdx.x] + sb[t] - v;  // exclusive
  if (i == 0) g_rs[NN] = NE;
}

__global__ void k_scatter() {
  int i = blockIdx.x * 256 + threadIdx.x;
  if (i < NE) {
    int d = g_dst[i];
    int p = atomicAdd(&g_cur[d], 1);
    g_sby[g_rs[d] + p] = g_src[i];   // store src directly, CSR order
  }
}

// ---------------- TF32 tensor-core GEMM: out[N,128] = A[N,K] @ W[K,128] ----------------
constexpr int M_BNA = 1, M_LEAKY = 2, M_ADDC = 4, M_BIAS = 16;

__device__ __forceinline__ void mma_tf32(float4& c, const unsigned a[4], const unsigned b[2]) {
  asm volatile(
      "mma.sync.aligned.m16n8k8.row.col.f32.tf32.tf32.f32 "
      "{%0,%1,%2,%3}, {%4,%5,%6,%7}, {%8,%9}, {%0,%1,%2,%3};"
      : "+f"(c.x), "+f"(c.y), "+f"(c.z), "+f"(c.w)
      : "r"(a[0]), "r"(a[1]), "r"(a[2]), "r"(a[3]), "r"(b[0]), "r"(b[1]));
}

// SEL: 0 -> A=Ap,    out=g_h1   (bias b_in, leaky)
//      1 -> A=g_h1,  out=g_t1   (BN1 affine on A)
//      2 -> A=g_skip,out=g_t2
//      3 -> A=g_skip,out=outp   (bias b_skip, addC=g_out2)
template <int K, int MODE, int SEL>
__global__ __launch_bounds__(256, 2) void k_gemm_tc(const float* __restrict__ Ap,
                                                    const float* __restrict__ W,
                                                    const float* __restrict__ bias,
                                                    float* __restrict__ outp) {
  const float* A = (SEL == 0) ? Ap : (SEL == 1) ? g_h1 : g_skip;
  float* out     = (SEL == 0) ? g_h1 : (SEL == 1) ? g_t1 : (SEL == 2) ? g_t2 : outp;

  // conflict-free by construction: As stride 36 (4r+c banks), Ws stride 136 (8k+n banks)
  __shared__ unsigned As[128 * 36];
  __shared__ unsigned Ws[32 * 136];

  int tid = threadIdx.x;
  int lane = tid & 31, wid = tid >> 5;
  int gr = lane >> 2, gc = lane & 3;     // mma group row / col-in-group
  int warp_m = wid & 3, warp_n = wid >> 2;
  int row0 = blockIdx.x * 128;

  float4 acc[2][8];
#pragma unroll
  for (int mt = 0; mt < 2; mt++)
#pragma unroll
    for (int nt = 0; nt < 8; nt++) acc[mt][nt] = make_float4(0.f, 0.f, 0.f, 0.f);

  for (int kc = 0; kc < K; kc += 32) {
#pragma unroll
    for (int i = 0; i < 4; i++) {
      int idx = tid * 4 + i * 1024;     // 0..4095
      int r = idx >> 5, c = idx & 31;
      int grow = row0 + r;
      float4 v = make_float4(0.f, 0.f, 0.f, 0.f);
      if (grow < NN) v = *(const float4*)(A + (size_t)grow * K + kc + c);
      if (MODE & M_BNA) {
        int kg = kc + c;
        v.x = fmaf(v.x, g_sc1[kg],     g_sh1[kg]);
        v.y = fmaf(v.y, g_sc1[kg + 1], g_sh1[kg + 1]);
        v.z = fmaf(v.z, g_sc1[kg + 2], g_sh1[kg + 2]);
        v.w = fmaf(v.w, g_sc1[kg + 3], g_sh1[kg + 3]);
      }
      unsigned* p = &As[r * 36 + c];
      p[0] = f2tf32(v.x); p[1] = f2tf32(v.y); p[2] = f2tf32(v.z); p[3] = f2tf32(v.w);
    }
#pragma unroll
    for (int i = 0; i < 4; i++) {
      int idx = tid * 4 + i * 1024;     // 0..4095
      int k = idx >> 7, n = idx & 127;
      float4 v = *(const float4*)(W + (size_t)(kc + k) * 128 + n);
      unsigned* p = &Ws[k * 136 + n];
      p[0] = f2tf32(v.x); p[1] = f2tf32(v.y); p[2] = f2tf32(v.z); p[3] = f2tf32(v.w);
    }
    __syncthreads();

#pragma unroll
    for (int kk = 0; kk < 32; kk += 8) {
      unsigned a[2][4];
#pragma unroll
      for (int mt = 0; mt < 2; mt++) {
        int rb = warp_m * 32 + mt * 16;
        a[mt][0] = As[(rb + gr)     * 36 + kk + gc];
        a[mt][1] = As[(rb + gr + 8) * 36 + kk + gc];
        a[mt][2] = As[(rb + gr)     * 36 + kk + gc + 4];
        a[mt][3] = As[(rb + gr + 8) * 36 + kk + gc + 4];
      }
      unsigned b[8][2];
#pragma unroll
      for (int nt = 0; nt < 8; nt++) {
        int n = warp_n * 64 + nt * 8 + gr;
        b[nt][0] = Ws[(kk + gc)     * 136 + n];
        b[nt][1] = Ws[(kk + gc + 4) * 136 + n];
      }
#pragma unroll
      for (int mt = 0; mt < 2; mt++)
#pragma unroll
        for (int nt = 0; nt < 8; nt++) mma_tf32(acc[mt][nt], a[mt], b[nt]);
    }
    __syncthreads();
  }

#pragma unroll
  for (int nt = 0; nt < 8; nt++) {
    int col = warp_n * 64 + nt * 8 + gc * 2;
    float2 bv = make_float2(0.f, 0.f);
    if (MODE & M_BIAS) bv = *(const float2*)(bias + col);
#pragma unroll
    for (int mt = 0; mt < 2; mt++) {
      int r0 = row0 + warp_m * 32 + mt * 16 + gr;
#pragma unroll
      for (int hh = 0; hh < 2; hh++) {
        int r = r0 + hh * 8;
        if (r < NN) {
          float2 v = hh ? make_float2(acc[mt][nt].z, acc[mt][nt].w)
                        : make_float2(acc[mt][nt].x, acc[mt][nt].y);
          if (MODE & M_BIAS) { v.x += bv.x; v.y += bv.y; }
          if (MODE & M_ADDC) {
            float2 cv = *(const float2*)(g_out2 + (size_t)r * 128 + col);
            v.x += cv.x; v.y += cv.y;
          }
          if (MODE & M_LEAKY) { v.x = lrelu(v.x); v.y = lrelu(v.y); }
          *(float2*)(out + (size_t)r * 128 + col) = v;
        }
      }
    }
  }
}

// ---------------- column stats (sum, sumsq) for BN ----------------
// L=1 reads g_h1 (device symbol resolved IN DEVICE CODE); L=2 reads the param.
template <int L>
__global__ __launch_bounds__(256) void k_colstats(const float* __restrict__ srcp) {
  const float* src = (L == 1) ? g_h1 : srcp;
  int col = threadIdx.x & 127;
  int half = threadIdx.x >> 7;
  float s = 0.f, q = 0.f;
  for (int i = 0; i < 256; i++) {
    int r = blockIdx.x * 512 + i * 2 + half;
    if (r < NN) {
      float v = src[(size_t)r * 128 + col];
      s += v;
      q += v * v;
    }
  }
  __shared__ float red[512];
  red[threadIdx.x] = s;
  red[256 + threadIdx.x] = q;
  __syncthreads();
  float* stats = (L == 1) ? g_stats1 : g_stats2;
  if (threadIdx.x < 128) {
    atomicAdd(&stats[threadIdx.x], red[threadIdx.x] + red[threadIdx.x + 128]);
    atomicAdd(&stats[128 + threadIdx.x], red[256 + threadIdx.x] + red[384 + threadIdx.x]);
  }
}

// ---------------- BN finalize: scale/shift from colsum/colsumsq ----------------
template <int L>
__global__ void k_bnfin(const float* __restrict__ gamma, const float* __restrict__ beta) {
  int i = threadIdx.x;
  const float* st = (L == 1) ? g_stats1 : g_stats2;
  float mean = st[i] * (1.f / NN);
  float var = st[128 + i] * (1.f / NN) - mean * mean;
  float sc = rsqrtf(var + 1e-5f) * gamma[i];
  float sh = beta[i] - mean * sc;
  if (L == 1) { g_sc1[i] = sc; g_sh1[i] = sh; }
  else        { g_sc2[i] = sc; g_sh2[i] = sh; }
}

// ---------------- attention per-node dot products ----------------
template <int H>
__global__ __launch_bounds__(256) void k_att(const float* __restrict__ avs,
                                             const float* __restrict__ avd) {
  int tid = threadIdx.x;
  int node = blockIdx.x * 2 + (tid >> 7);
  int j = tid & 127;
  const float* t = (H == 8) ? g_t1 : g_t2;
  float tv = t[(size_t)node * 128 + j];
  float ps = tv * avs[j];
  float pd = tv * avd[j];
#pragma unroll
  for (int o = 8; o; o >>= 1) {
    ps += __shfl_xor_sync(0xffffffffu, ps, o);
    pd += __shfl_xor_sync(0xffffffffu, pd, o);
  }
  if (H == 8) {
    if ((j & 15) == 0) {
      g_as1[node * 8 + (j >> 4)] = ps;
      g_ad1[node * 8 + (j >> 4)] = pd;
    }
  } else {
    __shared__ float sb[2][8][2];
    if ((j & 15) == 0) { sb[tid >> 7][j >> 4][0] = ps; sb[tid >> 7][j >> 4][1] = pd; }
    __syncthreads();
    if (j == 0) {
      float a = 0.f, b = 0.f;
#pragma unroll
      for (int s = 0; s < 8; s++) { a += sb[tid >> 7][s][0]; b += sb[tid >> 7][s][1]; }
      g_as2[node] = a;
      g_ad2[node] = b;
    }
  }
}

template <int H>
__device__ __forceinline__ void load_as(float* dst, const float* __restrict__ p, int s) {
  if constexpr (H == 8) {
    float4 a = __ldg((const float4*)(p + (size_t)s * 8));
    float4 b = __ldg((const float4*)(p + (size_t)s * 8 + 4));
    dst[0] = a.x; dst[1] = a.y; dst[2] = a.z; dst[3] = a.w;
    dst[4] = b.x; dst[5] = b.y; dst[6] = b.z; dst[7] = b.w;
  } else {
    dst[0] = __ldg(p + s);
  }
}

// ---------------- GAT aggregation: single sweep, online softmax ----------------
// one block (128 thr) per dst node; edges in chunks of 128
template <int H, bool LK>
__global__ __launch_bounds__(128) void k_gat(const float* __restrict__ bias) {
  const float* t   = (H == 8) ? g_t1  : g_t2;
  const float* asv = (H == 8) ? g_as1 : g_as2;
  const float* adv = (H == 8) ? g_ad1 : g_ad2;
  float* out       = (H == 8) ? g_skip : g_out2;

  int node = blockIdx.x, tid = threadIdx.x;
  int beg = g_rs[node];
  int cnt = g_rs[node + 1] - beg;
  int lane = tid & 31, warp = tid >> 5;
  int myh = (H == 8) ? (tid >> 4) : 0;

  float ad[H];
  load_as<H>(ad, adv, node);

  __shared__ float se[128 * H];     // alpha' = exp(e - m_running) per edge/head
  __shared__ int   ssrc[128];
  __shared__ float sred[4][H];

  float m[H], den[H];
#pragma unroll
  for (int h = 0; h < H; h++) { m[h] = -1e30f; den[h] = 0.f; }
  float acc = 0.f, acc2 = 0.f;

  for (int base = 0; base < cnt; base += 128) {
    int c = min(128, cnt - base);

    // logits for this chunk (one random as-gather per edge, total)
    float e[H];
    if (tid < c) {
      int s = __ldg(&g_sby[beg + base + tid]);
      ssrc[tid] = s;
      float av[H];
      load_as<H>(av, asv, s);
#pragma unroll
      for (int h = 0; h < H; h++) e[h] = lrelu(av[h] + ad[h]);
    } else {
#pragma unroll
      for (int h = 0; h < H; h++) e[h] = -1e30f;
    }

    // chunk max per head
    float cm[H];
#pragma unroll
    for (int h = 0; h < H; h++) {
      cm[h] = e[h];
#pragma unroll
      for (int o = 16; o; o >>= 1) cm[h] = fmaxf(cm[h], __shfl_xor_sync(0xffffffffu, cm[h], o));
    }
    if (lane == 0) {
#pragma unroll
      for (int h = 0; h < H; h++) sred[warp][h] = cm[h];
    }
    __syncthreads();
#pragma unroll
    for (int h = 0; h < H; h++)
      cm[h] = fmaxf(fmaxf(sred[0][h], sred[1][h]), fmaxf(sred[2][h], sred[3][h]));

    // online rescale
    float a_[H];
#pragma unroll
    for (int h = 0; h < H; h++) {
      float mn = fmaxf(m[h], cm[h]);
      float f = __expf(m[h] - mn);
      m[h] = mn;
      den[h] *= f;
      if (h == myh) { acc *= f; acc2 *= f; }
      a_[h] = (tid < c) ? __expf(e[h] - mn) : 0.f;
    }
    if (tid < c) {
#pragma unroll
      for (int h = 0; h < H; h++) se[tid * H + h] = a_[h];
    }
    __syncthreads();  // se visible; sred WAR-safe for reuse

    // chunk denominator sum per head
#pragma unroll
    for (int h = 0; h < H; h++) {
#pragma unroll
      for (int o = 16; o; o >>= 1) a_[h] += __shfl_xor_sync(0xffffffffu, a_[h], o);
    }
    if (lane == 0) {
#pragma unroll
      for (int h = 0; h < H; h++) sred[warp][h] = a_[h];
    }
    __syncthreads();
#pragma unroll
    for (int h = 0; h < H; h++)
      den[h] += sred[0][h] + sred[1][h] + sred[2][h] + sred[3][h];

    // weighted gather (thread = feature channel), unroll x4, dual accumulators
    int e2 = 0;
    for (; e2 + 4 <= c; e2 += 4) {
      float w0 = se[(e2 + 0) * H + myh], w1 = se[(e2 + 1) * H + myh];
      float w2 = se[(e2 + 2) * H + myh], w3 = se[(e2 + 3) * H + myh];
      int s0 = ssrc[e2], s1 = ssrc[e2 + 1], s2 = ssrc[e2 + 2], s3 = ssrc[e2 + 3];
      acc  = fmaf(w0, __ldg(&t[(size_t)s0 * 128 + tid]), acc);
      acc2 = fmaf(w1, __ldg(&t[(size_t)s1 * 128 + tid]), acc2);
      acc  = fmaf(w2, __ldg(&t[(size_t)s2 * 128 + tid]), acc);
      acc2 = fmaf(w3, __ldg(&t[(size_t)s3 * 128 + tid]), acc2);
    }
    for (; e2 < c; e2++)
      acc = fmaf(se[e2 * H + myh], __ldg(&t[(size_t)ssrc[e2] * 128 + tid]), acc);
    __syncthreads();  // before next chunk rewrites se/ssrc
  }

  float v = (acc + acc2) / fmaxf(den[myh], 1e-16f) + bias[tid];
  if (LK) v = lrelu(v);
  out[(size_t)node * 128 + tid] = v;
}

// ---------------- final: BN2 affine + L2 row normalize (in-place on d_out) ----------------
__global__ __launch_bounds__(128) void k_final(float* __restrict__ out) {
  int node = blockIdx.x, tid = threadIdx.x;
  float v = out[(size_t)node * 128 + tid] * g_sc2[tid] + g_sh2[tid];
  float q = v * v;
#pragma unroll
  for (int o = 16; o; o >>= 1) q += __shfl_xor_sync(0xffffffffu, q, o);
  __shared__ float sq[4];
  if ((tid & 31) == 0) sq[tid >> 5] = q;
  __syncthreads();
  float tot = sq[0] + sq[1] + sq[2] + sq[3];
  float r = 1.f / fmaxf(sqrtf(tot), 1e-12f);
  out[(size_t)node * 128 + tid] = v * r;
}

}  // namespace

extern "C" void kernel_launch(void* const* d_in, const int* in_sizes, int n_in,
                              void* d_out, int out_size) {
  const float* x        = (const float*)d_in[0];
  const float* W_in     = (const float*)d_in[1];
  const float* b_in     = (const float*)d_in[2];
  const float* gamma1   = (const float*)d_in[3];
  const float* beta1    = (const float*)d_in[4];
  const float* W1       = (const float*)d_in[5];
  const float* att_src1 = (const float*)d_in[6];
  const float* att_dst1 = (const float*)d_in[7];
  const float* bias1    = (const float*)d_in[8];
  const float* W2       = (const float*)d_in[9];
  const float* att_src2 = (const float*)d_in[10];
  const float* att_dst2 = (const float*)d_in[11];
  const float* bias2    = (const float*)d_in[12];
  const float* W_skip   = (const float*)d_in[13];
  const float* b_skip   = (const float*)d_in[14];
  const float* gamma2   = (const float*)d_in[15];
  const float* beta2    = (const float*)d_in[16];
  const void*  eidx     = d_in[17];
  float* out = (float*)d_out;

  // CSR build
  k_zero<<<(NN + 255) / 256, 256>>>(eidx);
  k_edges<<<(NE + 255) / 256, 256>>>(eidx);
  k_scan_a<<<NB, 1024>>>();
  k_scan_b<<<1, 1>>>();
  k_scan_c<<<NB, 1024>>>();
  k_scatter<<<(NE + 255) / 256, 256>>>();

  const int GB = (NN + 127) / 128;   // 391
  const int SB = (NN + 511) / 512;   // 98
  // h1 = leaky(x @ W_in + b_in), then BN1 stats
  k_gemm_tc<KIN, M_BIAS | M_LEAKY, 0><<<GB, 256>>>(x, W_in, b_in, nullptr);
  k_colstats<1><<<SB, 256>>>(nullptr);
  k_bnfin<1><<<1, 128>>>(gamma1, beta1);
  // t1 = BN1(h1) @ W1
  k_gemm_tc<128, M_BNA, 1><<<GB, 256>>>(nullptr, W1, nullptr, nullptr);
  // attention logits layer 1
  k_att<8><<<NN / 2, 256>>>(att_src1, att_dst1);
  // skip = leaky(gat1 + bias1)
  k_gat<8, true><<<NN, 128>>>(bias1);
  // t2 = skip @ W2
  k_gemm_tc<128, 0, 2><<<GB, 256>>>(nullptr, W2, nullptr, nullptr);
  // attention logits layer 2
  k_att<1><<<NN / 2, 256>>>(att_src2, att_dst2);
  // out2 = gat2 + bias2
  k_gat<1, false><<<NN, 128>>>(bias2);
  // pre = skip @ W_skip + b_skip + out2  (written to d_out), then BN2 stats
  k_gemm_tc<128, M_BIAS | M_ADDC, 3><<<GB, 256>>>(nullptr, W_skip, b_skip, out);
  k_colstats<2><<<SB, 256>>>(out);
  k_bnfin<2><<<1, 128>>>(gamma2, beta2);
  // BN2 affine + L2 normalize, in place
  k_final<<<NN, 128>>>(out);
}

// round 7
// speedup vs baseline: 1.5971x; 1.2913x over previous
#include <cuda_runtime.h>

namespace {

constexpr int NN  = 50000;   // nodes
constexpr int NE  = 800000;  // edges
constexpr int KIN = 256;     // in_dim
constexpr int NB  = (NN + 1023) / 1024;  // scan blocks = 49

// ---------------- scratch (static device memory; no allocations) ----------------
__device__ float g_h1[NN * 128];     // leaky(x@W_in+b_in)  (pre-BN1)
__device__ float g_t1[NN * 128];     // BN1(h1) @ W1
__device__ float g_skip[NN * 128];   // leaky(gat1 + bias1)
__device__ float g_t2[NN * 128];     // skip @ W2
__device__ float g_out2[NN * 128];   // gat2 + bias2
__device__ float g_as1[NN * 8];
__device__ float g_ad1[NN * 8];
__device__ float g_as2[NN];
__device__ float g_ad2[NN];
__device__ int   g_src[NE];
__device__ int   g_dst[NE];
__device__ int   g_sby[NE];          // src ids sorted by dst (CSR order)
__device__ int   g_deg[NN];
__device__ int   g_cur[NN];
__device__ int   g_rs[NN + 1];       // CSR row starts
__device__ int   g_bsum[NB];
__device__ int   g_boff[NB];
__device__ float g_stats1[256];      // [0:128) colsum, [128:256) colsumsq
__device__ float g_stats2[256];
__device__ float g_sc1[128], g_sh1[128], g_sc2[128], g_sh2[128];
__device__ int   g_is64;             // edge_index dtype flag (detected on device)

__device__ __forceinline__ float lrelu(float v) { return v >= 0.f ? v : 0.2f * v; }

__device__ __forceinline__ unsigned f2tf32(float f) {
  unsigned u;
  asm("cvt.rna.tf32.f32 %0, %1;" : "=r"(u) : "f"(f));
  return u;
}

// ---------------- setup: zero + dtype detect ----------------
__global__ void k_zero(const void* __restrict__ ei) {
  int i = blockIdx.x * 256 + threadIdx.x;
  if (i < NN) { g_deg[i] = 0; g_cur[i] = 0; }
  if (i < 256) { g_stats1[i] = 0.f; g_stats2[i] = 0.f; }
  if (blockIdx.x == 0 && threadIdx.x == 0) {
    const long long* p = (const long long*)ei;
    int ok = 1;
    for (int j = 0; j < 64; j++) {
      long long v = p[j];
      if (v < 0 || v >= NN) { ok = 0; break; }
    }
    g_is64 = ok;
  }
}

__global__ void k_edges(const void* __restrict__ ei) {
  int i = blockIdx.x * 256 + threadIdx.x;
  if (i < NE) {
    int s, d;
    if (g_is64) {
      const long long* p = (const long long*)ei;
      s = (int)p[i];
      d = (int)p[NE + i];
    } else {
      const int* p = (const int*)ei;
      s = p[i];
      d = p[NE + i];
    }
    if ((unsigned)s >= NN) s = 0;
    if ((unsigned)d >= NN) d = 0;
    g_src[i] = s;
    g_dst[i] = d;
    atomicAdd(&g_deg[d], 1);
  }
}

__global__ void k_scan_a() {
  int i = blockIdx.x * 1024 + threadIdx.x;
  int v = (i < NN) ? g_deg[i] : 0;
#pragma unroll
  for (int o = 16; o; o >>= 1) v += __shfl_xor_sync(0xffffffffu, v, o);
  __shared__ int sb[32];
  if ((threadIdx.x & 31) == 0) sb[threadIdx.x >> 5] = v;
  __syncthreads();
  if (threadIdx.x == 0) {
    int t = 0;
#pragma unroll
    for (int w = 0; w < 32; w++) t += sb[w];
    g_bsum[blockIdx.x] = t;
  }
}

__global__ void k_scan_b() {      // exclusive scan of NB=49 values, 64 threads
  int t = threadIdx.x;
  __shared__ int sb[64];
  sb[t] = (t < NB) ? g_bsum[t] : 0;
  __syncthreads();
#pragma unroll
  for (int o = 1; o < 64; o <<= 1) {
    int x = (t >= o) ? sb[t - o] : 0;
    __syncthreads();
    sb[t] += x;
    __syncthreads();
  }
  if (t < NB) g_boff[t] = sb[t] - g_bsum[t];
}

__global__ void k_scan_c() {
  int t = threadIdx.x;
  int i = blockIdx.x * 1024 + t;
  int v = (i < NN) ? g_deg[i] : 0;
  __shared__ int sb[1024];
  sb[t] = v;
  __syncthreads();
  for (int o = 1; o < 1024; o <<= 1) {
    int x = (t >= o) ? sb[t - o] : 0;
    __syncthreads();
    sb[t] += x;
    __syncthreads();
  }
  if (i < NN) g_rs[i] = g_boff[blockIdx.x] + sb[t] - v;  // exclusive
  if (i == 0) g_rs[NN] = NE;
}

__global__ void k_scatter() {
  int i = blockIdx.x * 256 + threadIdx.x;
  if (i < NE) {
    int d = g_dst[i];
    int p = atomicAdd(&g_cur[d], 1);
    g_sby[g_rs[d] + p] = g_src[i];   // store src directly, CSR order
  }
}

// ---------------- TF32 tensor-core GEMM: out[N,128] = A[N,K] @ W[K,128] ----------------
constexpr int M_BNA = 1, M_LEAKY = 2, M_ADDC = 4, M_BIAS = 16;

__device__ __forceinline__ void mma_tf32(float4& c, const unsigned a[4], const unsigned b[2]) {
  asm volatile(
      "mma.sync.aligned.m16n8k8.row.col.f32.tf32.tf32.f32 "
      "{%0,%1,%2,%3}, {%4,%5,%6,%7}, {%8,%9}, {%0,%1,%2,%3};"
      : "+f"(c.x), "+f"(c.y), "+f"(c.z), "+f"(c.w)
      : "r"(a[0]), "r"(a[1]), "r"(a[2]), "r"(a[3]), "r"(b[0]), "r"(b[1]));
}

// SEL: 0 -> A=Ap,    out=g_h1   (bias b_in, leaky)
//      1 -> A=g_h1,  out=g_t1   (BN1 affine on A)
//      2 -> A=g_skip,out=g_t2
//      3 -> A=g_skip,out=outp   (bias b_skip, addC=g_out2)
template <int K, int MODE, int SEL>
__global__ __launch_bounds__(256, 2) void k_gemm_tc(const float* __restrict__ Ap,
                                                    const float* __restrict__ W,
                                                    const float* __restrict__ bias,
                                                    float* __restrict__ outp) {
  const float* A = (SEL == 0) ? Ap : (SEL == 1) ? g_h1 : g_skip;
  float* out     = (SEL == 0) ? g_h1 : (SEL == 1) ? g_t1 : (SEL == 2) ? g_t2 : outp;

  __shared__ unsigned As[128 * 36];
  __shared__ unsigned Ws[32 * 136];

  int tid = threadIdx.x;
  int lane = tid & 31, wid = tid >> 5;
  int gr = lane >> 2, gc = lane & 3;
  int warp_m = wid & 3, warp_n = wid >> 2;
  int row0 = blockIdx.x * 128;

  float4 acc[2][8];
#pragma unroll
  for (int mt = 0; mt < 2; mt++)
#pragma unroll
    for (int nt = 0; nt < 8; nt++) acc[mt][nt] = make_float4(0.f, 0.f, 0.f, 0.f);

  for (int kc = 0; kc < K; kc += 32) {
#pragma unroll
    for (int i = 0; i < 4; i++) {
      int idx = tid * 4 + i * 1024;
      int r = idx >> 5, c = idx & 31;
      int grow = row0 + r;
      float4 v = make_float4(0.f, 0.f, 0.f, 0.f);
      if (grow < NN) v = *(const float4*)(A + (size_t)grow * K + kc + c);
      if (MODE & M_BNA) {
        int kg = kc + c;
        v.x = fmaf(v.x, g_sc1[kg],     g_sh1[kg]);
        v.y = fmaf(v.y, g_sc1[kg + 1], g_sh1[kg + 1]);
        v.z = fmaf(v.z, g_sc1[kg + 2], g_sh1[kg + 2]);
        v.w = fmaf(v.w, g_sc1[kg + 3], g_sh1[kg + 3]);
      }
      unsigned* p = &As[r * 36 + c];
      p[0] = f2tf32(v.x); p[1] = f2tf32(v.y); p[2] = f2tf32(v.z); p[3] = f2tf32(v.w);
    }
#pragma unroll
    for (int i = 0; i < 4; i++) {
      int idx = tid * 4 + i * 1024;
      int k = idx >> 7, n = idx & 127;
      float4 v = *(const float4*)(W + (size_t)(kc + k) * 128 + n);
      unsigned* p = &Ws[k * 136 + n];
      p[0] = f2tf32(v.x); p[1] = f2tf32(v.y); p[2] = f2tf32(v.z); p[3] = f2tf32(v.w);
    }
    __syncthreads();

#pragma unroll
    for (int kk = 0; kk < 32; kk += 8) {
      unsigned a[2][4];
#pragma unroll
      for (int mt = 0; mt < 2; mt++) {
        int rb = warp_m * 32 + mt * 16;
        a[mt][0] = As[(rb + gr)     * 36 + kk + gc];
        a[mt][1] = As[(rb + gr + 8) * 36 + kk + gc];
        a[mt][2] = As[(rb + gr)     * 36 + kk + gc + 4];
        a[mt][3] = As[(rb + gr + 8) * 36 + kk + gc + 4];
      }
      unsigned b[8][2];
#pragma unroll
      for (int nt = 0; nt < 8; nt++) {
        int n = warp_n * 64 + nt * 8 + gr;
        b[nt][0] = Ws[(kk + gc)     * 136 + n];
        b[nt][1] = Ws[(kk + gc + 4) * 136 + n];
      }
#pragma unroll
      for (int mt = 0; mt < 2; mt++)
#pragma unroll
        for (int nt = 0; nt < 8; nt++) mma_tf32(acc[mt][nt], a[mt], b[nt]);
    }
    __syncthreads();
  }

#pragma unroll
  for (int nt = 0; nt < 8; nt++) {
    int col = warp_n * 64 + nt * 8 + gc * 2;
    float2 bv = make_float2(0.f, 0.f);
    if (MODE & M_BIAS) bv = *(const float2*)(bias + col);
#pragma unroll
    for (int mt = 0; mt < 2; mt++) {
      int r0 = row0 + warp_m * 32 + mt * 16 + gr;
#pragma unroll
      for (int hh = 0; hh < 2; hh++) {
        int r = r0 + hh * 8;
        if (r < NN) {
          float2 v = hh ? make_float2(acc[mt][nt].z, acc[mt][nt].w)
                        : make_float2(acc[mt][nt].x, acc[mt][nt].y);
          if (MODE & M_BIAS) { v.x += bv.x; v.y += bv.y; }
          if (MODE & M_ADDC) {
            float2 cv = *(const float2*)(g_out2 + (size_t)r * 128 + col);
            v.x += cv.x; v.y += cv.y;
          }
          if (MODE & M_LEAKY) { v.x = lrelu(v.x); v.y = lrelu(v.y); }
          *(float2*)(out + (size_t)r * 128 + col) = v;
        }
      }
    }
  }
}

// ---------------- column stats (sum, sumsq) for BN ----------------
template <int L>
__global__ __launch_bounds__(256) void k_colstats(const float* __restrict__ srcp) {
  const float* src = (L == 1) ? g_h1 : srcp;
  int col = threadIdx.x & 127;
  int half = threadIdx.x >> 7;
  float s = 0.f, q = 0.f;
  for (int i = 0; i < 256; i++) {
    int r = blockIdx.x * 512 + i * 2 + half;
    if (r < NN) {
      float v = src[(size_t)r * 128 + col];
      s += v;
      q += v * v;
    }
  }
  __shared__ float red[512];
  red[threadIdx.x] = s;
  red[256 + threadIdx.x] = q;
  __syncthreads();
  float* stats = (L == 1) ? g_stats1 : g_stats2;
  if (threadIdx.x < 128) {
    atomicAdd(&stats[threadIdx.x], red[threadIdx.x] + red[threadIdx.x + 128]);
    atomicAdd(&stats[128 + threadIdx.x], red[256 + threadIdx.x] + red[384 + threadIdx.x]);
  }
}

// ---------------- BN finalize ----------------
template <int L>
__global__ void k_bnfin(const float* __restrict__ gamma, const float* __restrict__ beta) {
  int i = threadIdx.x;
  const float* st = (L == 1) ? g_stats1 : g_stats2;
  float mean = st[i] * (1.f / NN);
  float var = st[128 + i] * (1.f / NN) - mean * mean;
  float sc = rsqrtf(var + 1e-5f) * gamma[i];
  float sh = beta[i] - mean * sc;
  if (L == 1) { g_sc1[i] = sc; g_sh1[i] = sh; }
  else        { g_sc2[i] = sc; g_sh2[i] = sh; }
}

// ---------------- attention per-node dot products ----------------
template <int H>
__global__ __launch_bounds__(256) void k_att(const float* __restrict__ avs,
                                             const float* __restrict__ avd) {
  int tid = threadIdx.x;
  int node = blockIdx.x * 2 + (tid >> 7);
  int j = tid & 127;
  const float* t = (H == 8) ? g_t1 : g_t2;
  float tv = t[(size_t)node * 128 + j];
  float ps = tv * avs[j];
  float pd = tv * avd[j];
#pragma unroll
  for (int o = 8; o; o >>= 1) {
    ps += __shfl_xor_sync(0xffffffffu, ps, o);
    pd += __shfl_xor_sync(0xffffffffu, pd, o);
  }
  if (H == 8) {
    if ((j & 15) == 0) {
      g_as1[node * 8 + (j >> 4)] = ps;
      g_ad1[node * 8 + (j >> 4)] = pd;
    }
  } else {
    __shared__ float sb[2][8][2];
    if ((j & 15) == 0) { sb[tid >> 7][j >> 4][0] = ps; sb[tid >> 7][j >> 4][1] = pd; }
    __syncthreads();
    if (j == 0) {
      float a = 0.f, b = 0.f;
#pragma unroll
      for (int s = 0; s < 8; s++) { a += sb[tid >> 7][s][0]; b += sb[tid >> 7][s][1]; }
      g_as2[node] = a;
      g_ad2[node] = b;
    }
  }
}

template <int H>
__device__ __forceinline__ void load_as(float* dst, const float* __restrict__ p, int s) {
  if constexpr (H == 8) {
    float4 a = __ldg((const float4*)(p + (size_t)s * 8));
    float4 b = __ldg((const float4*)(p + (size_t)s * 8 + 4));
    dst[0] = a.x; dst[1] = a.y; dst[2] = a.z; dst[3] = a.w;
    dst[4] = b.x; dst[5] = b.y; dst[6] = b.z; dst[7] = b.w;
  } else {
    dst[0] = __ldg(p + s);
  }
}

// ---------------- GAT aggregation: WARP per node, online softmax ----------------
// 8 warps/block; lane l owns channels 4l..4l+3 (one float4 = full coalesced row).
// For H=8 those channels sit inside head l/4. No __syncthreads anywhere.
template <int H, bool LK>
__global__ __launch_bounds__(256) void k_gat(const float* __restrict__ bias) {
  const float* t   = (H == 8) ? g_t1  : g_t2;
  const float* asv = (H == 8) ? g_as1 : g_as2;
  const float* adv = (H == 8) ? g_ad1 : g_ad2;
  float* out       = (H == 8) ? g_skip : g_out2;

  int lane = threadIdx.x & 31, warp = threadIdx.x >> 5;
  int node = blockIdx.x * 8 + warp;
  if (node >= NN) return;
  int beg = g_rs[node];
  int cnt = g_rs[node + 1] - beg;
  int myh = (H == 8) ? (lane >> 2) : 0;

  __shared__ float salpha[8][H * 33];   // stride 33 -> conflict-free reads by head

  float ad[H];
  load_as<H>(ad, adv, node);

  float m[H], den[H];
#pragma unroll
  for (int h = 0; h < H; h++) { m[h] = -1e30f; den[h] = 0.f; }
  float4 acc = make_float4(0.f, 0.f, 0.f, 0.f);

  for (int base = 0; base < cnt; base += 32) {
    int c = min(32, cnt - base);

    // logits (one random as-gather per edge, once)
    int s = 0;
    float e[H];
    if (lane < c) {
      s = __ldg(&g_sby[beg + base + lane]);
      float av[H];
      load_as<H>(av, asv, s);
#pragma unroll
      for (int h = 0; h < H; h++) e[h] = lrelu(av[h] + ad[h]);
    } else {
#pragma unroll
      for (int h = 0; h < H; h++) e[h] = -1e30f;
    }

    // chunk max (warp allreduce)
    float cm[H];
#pragma unroll
    for (int h = 0; h < H; h++) {
      cm[h] = e[h];
#pragma unroll
      for (int o = 16; o; o >>= 1) cm[h] = fmaxf(cm[h], __shfl_xor_sync(0xffffffffu, cm[h], o));
    }

    // online rescale + alpha' store
    float a_[H];
#pragma unroll
    for (int h = 0; h < H; h++) {
      float mn = fmaxf(m[h], cm[h]);
      float f = __expf(m[h] - mn);
      m[h] = mn;
      den[h] *= f;
      if (h == myh) { acc.x *= f; acc.y *= f; acc.z *= f; acc.w *= f; }
      a_[h] = (lane < c) ? __expf(e[h] - mn) : 0.f;
      salpha[warp][h * 33 + lane] = a_[h];
    }

    // chunk denominator (warp allreduce)
#pragma unroll
    for (int h = 0; h < H; h++) {
      float sum = a_[h];
#pragma unroll
      for (int o = 16; o; o >>= 1) sum += __shfl_xor_sync(0xffffffffu, sum, o);
      den[h] += sum;
    }
    __syncwarp();

    // weighted gather: per edge, one coalesced 128B row read
    const float* sa = &salpha[warp][myh * 33];
#pragma unroll 4
    for (int j = 0; j < c; j++) {
      int sj = __shfl_sync(0xffffffffu, s, j);
      float w = sa[j];
      float4 tv = __ldg((const float4*)(t + (size_t)sj * 128 + lane * 4));
      acc.x = fmaf(w, tv.x, acc.x);
      acc.y = fmaf(w, tv.y, acc.y);
      acc.z = fmaf(w, tv.z, acc.z);
      acc.w = fmaf(w, tv.w, acc.w);
    }
    __syncwarp();
  }

  float inv = 1.f / fmaxf(den[myh], 1e-16f);
  float4 bv = *(const float4*)(bias + lane * 4);
  float4 v;
  v.x = acc.x * inv + bv.x;
  v.y = acc.y * inv + bv.y;
  v.z = acc.z * inv + bv.z;
  v.w = acc.w * inv + bv.w;
  if (LK) { v.x = lrelu(v.x); v.y = lrelu(v.y); v.z = lrelu(v.z); v.w = lrelu(v.w); }
  *(float4*)(out + (size_t)node * 128 + lane * 4) = v;
}

// ---------------- final: BN2 affine + L2 row normalize (in-place on d_out) ----------------
__global__ __launch_bounds__(128) void k_final(float* __restrict__ out) {
  int node = blockIdx.x, tid = threadIdx.x;
  float v = out[(size_t)node * 128 + tid] * g_sc2[tid] + g_sh2[tid];
  float q = v * v;
#pragma unroll
  for (int o = 16; o; o >>= 1) q += __shfl_xor_sync(0xffffffffu, q, o);
  __shared__ float sq[4];
  if ((tid & 31) == 0) sq[tid >> 5] = q;
  __syncthreads();
  float tot = sq[0] + sq[1] + sq[2] + sq[3];
  float r = 1.f / fmaxf(sqrtf(tot), 1e-12f);
  out[(size_t)node * 128 + tid] = v * r;
}

}  // namespace

extern "C" void kernel_launch(void* const* d_in, const int* in_sizes, int n_in,
                              void* d_out, int out_size) {
  const float* x        = (const float*)d_in[0];
  const float* W_in     = (const float*)d_in[1];
  const float* b_in     = (const float*)d_in[2];
  const float* gamma1   = (const float*)d_in[3];
  const float* beta1    = (const float*)d_in[4];
  const float* W1       = (const float*)d_in[5];
  const float* att_src1 = (const float*)d_in[6];
  const float* att_dst1 = (const float*)d_in[7];
  const float* bias1    = (const float*)d_in[8];
  const float* W2       = (const float*)d_in[9];
  const float* att_src2 = (const float*)d_in[10];
  const float* att_dst2 = (const float*)d_in[11];
  const float* bias2    = (const float*)d_in[12];
  const float* W_skip   = (const float*)d_in[13];
  const float* b_skip   = (const float*)d_in[14];
  const float* gamma2   = (const float*)d_in[15];
  const float* beta2    = (const float*)d_in[16];
  const void*  eidx     = d_in[17];
  float* out = (float*)d_out;

  // CSR build
  k_zero<<<(NN + 255) / 256, 256>>>(eidx);
  k_edges<<<(NE + 255) / 256, 256>>>(eidx);
  k_scan_a<<<NB, 1024>>>();
  k_scan_b<<<1, 64>>>();
  k_scan_c<<<NB, 1024>>>();
  k_scatter<<<(NE + 255) / 256, 256>>>();

  const int GB = (NN + 127) / 128;   // 391
  const int SB = (NN + 511) / 512;   // 98
  const int AB = (NN + 7) / 8;       // 6250 (warp-per-node gat)
  // h1 = leaky(x @ W_in + b_in), then BN1 stats
  k_gemm_tc<KIN, M_BIAS | M_LEAKY, 0><<<GB, 256>>>(x, W_in, b_in, nullptr);
  k_colstats<1><<<SB, 256>>>(nullptr);
  k_bnfin<1><<<1, 128>>>(gamma1, beta1);
  // t1 = BN1(h1) @ W1
  k_gemm_tc<128, M_BNA, 1><<<GB, 256>>>(nullptr, W1, nullptr, nullptr);
  // attention logits layer 1
  k_att<8><<<NN / 2, 256>>>(att_src1, att_dst1);
  // skip = leaky(gat1 + bias1)
  k_gat<8, true><<<AB, 256>>>(bias1);
  // t2 = skip @ W2
  k_gemm_tc<128, 0, 2><<<GB, 256>>>(nullptr, W2, nullptr, nullptr);
  // attention logits layer 2
  k_att<1><<<NN / 2, 256>>>(att_src2, att_dst2);
  // out2 = gat2 + bias2
  k_gat<1, false><<<AB, 256>>>(bias2);
  // pre = skip @ W_skip + b_skip + out2  (written to d_out), then BN2 stats
  k_gemm_tc<128, M_BIAS | M_ADDC, 3><<<GB, 256>>>(nullptr, W_skip, b_skip, out);
  k_colstats<2><<<SB, 256>>>(out);
  k_bnfin<2><<<1, 128>>>(gamma2, beta2);
  // BN2 affine + L2 normalize, in place
  k_final<<<NN, 128>>>(out);
}

// round 8
// speedup vs baseline: 1.6665x; 1.0434x over previous
#include <cuda_runtime.h>

namespace {

constexpr int NN  = 50000;   // nodes
constexpr int NE  = 800000;  // edges
constexpr int KIN = 256;     // in_dim
constexpr int NB  = (NN + 1023) / 1024;  // scan blocks = 49

// ---------------- scratch (static device memory; no allocations) ----------------
__device__ float g_h1[NN * 128];     // leaky(x@W_in+b_in)  (pre-BN1)
__device__ float g_t1[NN * 128];     // BN1(h1) @ W1
__device__ float g_skip[NN * 128];   // leaky(gat1 + bias1)
__device__ float g_t2[NN * 128];     // skip @ W2
__device__ float g_out2[NN * 128];   // gat2 + bias2
__device__ float g_as1[NN * 8];
__device__ float g_ad1[NN * 8];
__device__ float g_as2[NN];
__device__ float g_ad2[NN];
__device__ int   g_src[NE];
__device__ int   g_dst[NE];
__device__ int   g_sby[NE];          // src ids sorted by dst (CSR order)
__device__ int   g_deg[NN];
__device__ int   g_cur[NN];
__device__ int   g_rs[NN + 1];       // CSR row starts (disjoint regions, deg-sized)
__device__ int   g_ctr;              // CSR region allocator
__device__ float g_stats1[256];      // [0:128) colsum, [128:256) colsumsq
__device__ float g_stats2[256];
__device__ float g_sc1[128], g_sh1[128], g_sc2[128], g_sh2[128];
__device__ int   g_is64;             // edge_index dtype flag (detected on device)

__device__ __forceinline__ float lrelu(float v) { return v >= 0.f ? v : 0.2f * v; }

__device__ __forceinline__ unsigned f2tf32(float f) {
  unsigned u;
  asm("cvt.rna.tf32.f32 %0, %1;" : "=r"(u) : "f"(f));
  return u;
}

// ---------------- setup: zero + dtype detect ----------------
__global__ void k_zero(const void* __restrict__ ei) {
  int i = blockIdx.x * 256 + threadIdx.x;
  if (i < NN) { g_deg[i] = 0; g_cur[i] = 0; }
  if (i < 256) { g_stats1[i] = 0.f; g_stats2[i] = 0.f; }
  if (blockIdx.x == 0 && threadIdx.x == 0) {
    g_ctr = 0;
    const long long* p = (const long long*)ei;
    int ok = 1;
    for (int j = 0; j < 64; j++) {
      long long v = p[j];
      if (v < 0 || v >= NN) { ok = 0; break; }
    }
    g_is64 = ok;
  }
}

__global__ void k_edges(const void* __restrict__ ei) {
  int i = blockIdx.x * 256 + threadIdx.x;
  if (i < NE) {
    int s, d;
    if (g_is64) {
      const long long* p = (const long long*)ei;
      s = (int)p[i];
      d = (int)p[NE + i];
    } else {
      const int* p = (const int*)ei;
      s = p[i];
      d = p[NE + i];
    }
    if ((unsigned)s >= NN) s = 0;
    if ((unsigned)d >= NN) d = 0;
    g_src[i] = s;
    g_dst[i] = d;
    atomicAdd(&g_deg[d], 1);
  }
}

// fused scan: each block scans 1024 degrees locally, claims base via atomicAdd.
// CSR regions are contiguous per node, disjoint across blocks (order irrelevant).
__global__ void k_scan() {
  int t = threadIdx.x;
  int i = blockIdx.x * 1024 + t;
  int v = (i < NN) ? g_deg[i] : 0;
  __shared__ int sb[1024];
  __shared__ int sbase;
  sb[t] = v;
  __syncthreads();
  for (int o = 1; o < 1024; o <<= 1) {
    int x = (t >= o) ? sb[t - o] : 0;
    __syncthreads();
    sb[t] += x;
    __syncthreads();
  }
  if (t == 1023) sbase = atomicAdd(&g_ctr, sb[1023]);
  __syncthreads();
  if (i < NN) g_rs[i] = sbase + sb[t] - v;   // exclusive within block + base
}

__global__ void k_scatter() {
  int i = blockIdx.x * 256 + threadIdx.x;
  if (i < NE) {
    int d = g_dst[i];
    int p = atomicAdd(&g_cur[d], 1);
    g_sby[g_rs[d] + p] = g_src[i];   // store src directly, CSR order
  }
}

// ---------------- TF32 tensor-core GEMM: out[N,128] = A[N,K] @ W[K,128] ----------------
constexpr int M_BNA = 1, M_LEAKY = 2, M_ADDC = 4, M_BIAS = 16;

__device__ __forceinline__ void mma_tf32(float4& c, const unsigned a[4], const unsigned b[2]) {
  asm volatile(
      "mma.sync.aligned.m16n8k8.row.col.f32.tf32.tf32.f32 "
      "{%0,%1,%2,%3}, {%4,%5,%6,%7}, {%8,%9}, {%0,%1,%2,%3};"
      : "+f"(c.x), "+f"(c.y), "+f"(c.z), "+f"(c.w)
      : "r"(a[0]), "r"(a[1]), "r"(a[2]), "r"(a[3]), "r"(b[0]), "r"(b[1]));
}

// SEL: 0 -> A=Ap,    out=g_h1   (bias b_in, leaky)
//      1 -> A=g_h1,  out=g_t1   (BN1 affine on A)
//      2 -> A=g_skip,out=g_t2
//      3 -> A=g_skip,out=outp   (bias b_skip, addC=g_out2)
template <int K, int MODE, int SEL>
__global__ __launch_bounds__(256, 2) void k_gemm_tc(const float* __restrict__ Ap,
                                                    const float* __restrict__ W,
                                                    const float* __restrict__ bias,
                                                    float* __restrict__ outp) {
  const float* A = (SEL == 0) ? Ap : (SEL == 1) ? g_h1 : g_skip;
  float* out     = (SEL == 0) ? g_h1 : (SEL == 1) ? g_t1 : (SEL == 2) ? g_t2 : outp;

  __shared__ unsigned As[128 * 36];
  __shared__ unsigned Ws[32 * 136];

  int tid = threadIdx.x;
  int lane = tid & 31, wid = tid >> 5;
  int gr = lane >> 2, gc = lane & 3;
  int warp_m = wid & 3, warp_n = wid >> 2;
  int row0 = blockIdx.x * 128;

  float4 acc[2][8];
#pragma unroll
  for (int mt = 0; mt < 2; mt++)
#pragma unroll
    for (int nt = 0; nt < 8; nt++) acc[mt][nt] = make_float4(0.f, 0.f, 0.f, 0.f);

  for (int kc = 0; kc < K; kc += 32) {
#pragma unroll
    for (int i = 0; i < 4; i++) {
      int idx = tid * 4 + i * 1024;
      int r = idx >> 5, c = idx & 31;
      int grow = row0 + r;
      float4 v = make_float4(0.f, 0.f, 0.f, 0.f);
      if (grow < NN) v = *(const float4*)(A + (size_t)grow * K + kc + c);
      if (MODE & M_BNA) {
        int kg = kc + c;
        v.x = fmaf(v.x, g_sc1[kg],     g_sh1[kg]);
        v.y = fmaf(v.y, g_sc1[kg + 1], g_sh1[kg + 1]);
        v.z = fmaf(v.z, g_sc1[kg + 2], g_sh1[kg + 2]);
        v.w = fmaf(v.w, g_sc1[kg + 3], g_sh1[kg + 3]);
      }
      unsigned* p = &As[r * 36 + c];
      p[0] = f2tf32(v.x); p[1] = f2tf32(v.y); p[2] = f2tf32(v.z); p[3] = f2tf32(v.w);
    }
#pragma unroll
    for (int i = 0; i < 4; i++) {
      int idx = tid * 4 + i * 1024;
      int k = idx >> 7, n = idx & 127;
      float4 v = *(const float4*)(W + (size_t)(kc + k) * 128 + n);
      unsigned* p = &Ws[k * 136 + n];
      p[0] = f2tf32(v.x); p[1] = f2tf32(v.y); p[2] = f2tf32(v.z); p[3] = f2tf32(v.w);
    }
    __syncthreads();

#pragma unroll
    for (int kk = 0; kk < 32; kk += 8) {
      unsigned a[2][4];
#pragma unroll
      for (int mt = 0; mt < 2; mt++) {
        int rb = warp_m * 32 + mt * 16;
        a[mt][0] = As[(rb + gr)     * 36 + kk + gc];
        a[mt][1] = As[(rb + gr + 8) * 36 + kk + gc];
        a[mt][2] = As[(rb + gr)     * 36 + kk + gc + 4];
        a[mt][3] = As[(rb + gr + 8) * 36 + kk + gc + 4];
      }
      unsigned b[8][2];
#pragma unroll
      for (int nt = 0; nt < 8; nt++) {
        int n = warp_n * 64 + nt * 8 + gr;
        b[nt][0] = Ws[(kk + gc)     * 136 + n];
        b[nt][1] = Ws[(kk + gc + 4) * 136 + n];
      }
#pragma unroll
      for (int mt = 0; mt < 2; mt++)
#pragma unroll
        for (int nt = 0; nt < 8; nt++) mma_tf32(acc[mt][nt], a[mt], b[nt]);
    }
    __syncthreads();
  }

#pragma unroll
  for (int nt = 0; nt < 8; nt++) {
    int col = warp_n * 64 + nt * 8 + gc * 2;
    float2 bv = make_float2(0.f, 0.f);
    if (MODE & M_BIAS) bv = *(const float2*)(bias + col);
#pragma unroll
    for (int mt = 0; mt < 2; mt++) {
      int r0 = row0 + warp_m * 32 + mt * 16 + gr;
#pragma unroll
      for (int hh = 0; hh < 2; hh++) {
        int r = r0 + hh * 8;
        if (r < NN) {
          float2 v = hh ? make_float2(acc[mt][nt].z, acc[mt][nt].w)
                        : make_float2(acc[mt][nt].x, acc[mt][nt].y);
          if (MODE & M_BIAS) { v.x += bv.x; v.y += bv.y; }
          if (MODE & M_ADDC) {
            float2 cv = *(const float2*)(g_out2 + (size_t)r * 128 + col);
            v.x += cv.x; v.y += cv.y;
          }
          if (MODE & M_LEAKY) { v.x = lrelu(v.x); v.y = lrelu(v.y); }
          *(float2*)(out + (size_t)r * 128 + col) = v;
        }
      }
    }
  }
}

// ---------------- column stats (sum, sumsq) for BN ----------------
template <int L>
__global__ __launch_bounds__(256) void k_colstats(const float* __restrict__ srcp) {
  const float* src = (L == 1) ? g_h1 : srcp;
  int col = threadIdx.x & 127;
  int half = threadIdx.x >> 7;
  float s = 0.f, q = 0.f;
  for (int i = 0; i < 256; i++) {
    int r = blockIdx.x * 512 + i * 2 + half;
    if (r < NN) {
      float v = src[(size_t)r * 128 + col];
      s += v;
      q += v * v;
    }
  }
  __shared__ float red[512];
  red[threadIdx.x] = s;
  red[256 + threadIdx.x] = q;
  __syncthreads();
  float* stats = (L == 1) ? g_stats1 : g_stats2;
  if (threadIdx.x < 128) {
    atomicAdd(&stats[threadIdx.x], red[threadIdx.x] + red[threadIdx.x + 128]);
    atomicAdd(&stats[128 + threadIdx.x], red[256 + threadIdx.x] + red[384 + threadIdx.x]);
  }
}

// ---------------- BN finalize ----------------
template <int L>
__global__ void k_bnfin(const float* __restrict__ gamma, const float* __restrict__ beta) {
  int i = threadIdx.x;
  const float* st = (L == 1) ? g_stats1 : g_stats2;
  float mean = st[i] * (1.f / NN);
  float var = st[128 + i] * (1.f / NN) - mean * mean;
  float sc = rsqrtf(var + 1e-5f) * gamma[i];
  float sh = beta[i] - mean * sc;
  if (L == 1) { g_sc1[i] = sc; g_sh1[i] = sh; }
  else        { g_sc2[i] = sc; g_sh2[i] = sh; }
}

// ---------------- attention per-node dot products ----------------
template <int H>
__global__ __launch_bounds__(256) void k_att(const float* __restrict__ avs,
                                             const float* __restrict__ avd) {
  int tid = threadIdx.x;
  int node = blockIdx.x * 2 + (tid >> 7);
  int j = tid & 127;
  const float* t = (H == 8) ? g_t1 : g_t2;
  float tv = t[(size_t)node * 128 + j];
  float ps = tv * avs[j];
  float pd = tv * avd[j];
#pragma unroll
  for (int o = 8; o; o >>= 1) {
    ps += __shfl_xor_sync(0xffffffffu, ps, o);
    pd += __shfl_xor_sync(0xffffffffu, pd, o);
  }
  if (H == 8) {
    if ((j & 15) == 0) {
      g_as1[node * 8 + (j >> 4)] = ps;
      g_ad1[node * 8 + (j >> 4)] = pd;
    }
  } else {
    __shared__ float sb[2][8][2];
    if ((j & 15) == 0) { sb[tid >> 7][j >> 4][0] = ps; sb[tid >> 7][j >> 4][1] = pd; }
    __syncthreads();
    if (j == 0) {
      float a = 0.f, b = 0.f;
#pragma unroll
      for (int s = 0; s < 8; s++) { a += sb[tid >> 7][s][0]; b += sb[tid >> 7][s][1]; }
      g_as2[node] = a;
      g_ad2[node] = b;
    }
  }
}

template <int H>
__device__ __forceinline__ void load_as(float* dst, const float* __restrict__ p, int s) {
  if constexpr (H == 8) {
    float4 a = __ldg((const float4*)(p + (size_t)s * 8));
    float4 b = __ldg((const float4*)(p + (size_t)s * 8 + 4));
    dst[0] = a.x; dst[1] = a.y; dst[2] = a.z; dst[3] = a.w;
    dst[4] = b.x; dst[5] = b.y; dst[6] = b.z; dst[7] = b.w;
  } else {
    dst[0] = __ldg(p + s);
  }
}

// ---------------- GAT aggregation: WARP per node, online softmax ----------------
template <int H, bool LK>
__global__ __launch_bounds__(256) void k_gat(const float* __restrict__ bias) {
  const float* t   = (H == 8) ? g_t1  : g_t2;
  const float* asv = (H == 8) ? g_as1 : g_as2;
  const float* adv = (H == 8) ? g_ad1 : g_ad2;
  float* out       = (H == 8) ? g_skip : g_out2;

  int lane = threadIdx.x & 31, warp = threadIdx.x >> 5;
  int node = blockIdx.x * 8 + warp;
  if (node >= NN) return;
  int beg = g_rs[node];
  int cnt = g_deg[node];
  int myh = (H == 8) ? (lane >> 2) : 0;

  __shared__ float salpha[8][H * 33];

  float ad[H];
  load_as<H>(ad, adv, node);

  float m[H], den[H];
#pragma unroll
  for (int h = 0; h < H; h++) { m[h] = -1e30f; den[h] = 0.f; }
  float4 acc = make_float4(0.f, 0.f, 0.f, 0.f);

  for (int base = 0; base < cnt; base += 32) {
    int c = min(32, cnt - base);

    int s = 0;
    float e[H];
    if (lane < c) {
      s = __ldg(&g_sby[beg + base + lane]);
      float av[H];
      load_as<H>(av, asv, s);
#pragma unroll
      for (int h = 0; h < H; h++) e[h] = lrelu(av[h] + ad[h]);
    } else {
#pragma unroll
      for (int h = 0; h < H; h++) e[h] = -1e30f;
    }

    float cm[H];
#pragma unroll
    for (int h = 0; h < H; h++) {
      cm[h] = e[h];
#pragma unroll
      for (int o = 16; o; o >>= 1) cm[h] = fmaxf(cm[h], __shfl_xor_sync(0xffffffffu, cm[h], o));
    }

    float a_[H];
#pragma unroll
    for (int h = 0; h < H; h++) {
      float mn = fmaxf(m[h], cm[h]);
      float f = __expf(m[h] - mn);
      m[h] = mn;
      den[h] *= f;
      if (h == myh) { acc.x *= f; acc.y *= f; acc.z *= f; acc.w *= f; }
      a_[h] = (lane < c) ? __expf(e[h] - mn) : 0.f;
      salpha[warp][h * 33 + lane] = a_[h];
    }

#pragma unroll
    for (int h = 0; h < H; h++) {
      float sum = a_[h];
#pragma unroll
      for (int o = 16; o; o >>= 1) sum += __shfl_xor_sync(0xffffffffu, sum, o);
      den[h] += sum;
    }
    __syncwarp();

    const float* sa = &salpha[warp][myh * 33];
#pragma unroll 4
    for (int j = 0; j < c; j++) {
      int sj = __shfl_sync(0xffffffffu, s, j);
      float w = sa[j];
      float4 tv = __ldg((const float4*)(t + (size_t)sj * 128 + lane * 4));
      acc.x = fmaf(w, tv.x, acc.x);
      acc.y = fmaf(w, tv.y, acc.y);
      acc.z = fmaf(w, tv.z, acc.z);
      acc.w = fmaf(w, tv.w, acc.w);
    }
    __syncwarp();
  }

  float inv = 1.f / fmaxf(den[myh], 1e-16f);
  float4 bv = *(const float4*)(bias + lane * 4);
  float4 v;
  v.x = acc.x * inv + bv.x;
  v.y = acc.y * inv + bv.y;
  v.z = acc.z * inv + bv.z;
  v.w = acc.w * inv + bv.w;
  if (LK) { v.x = lrelu(v.x); v.y = lrelu(v.y); v.z = lrelu(v.z); v.w = lrelu(v.w); }
  *(float4*)(out + (size_t)node * 128 + lane * 4) = v;
}

// ---------------- final: BN2 affine + L2 row normalize (2 nodes/block) ----------------
__global__ __launch_bounds__(256) void k_final(float* __restrict__ out) {
  int node = blockIdx.x * 2 + (threadIdx.x >> 7);
  int tid = threadIdx.x & 127;
  if (node >= NN) return;
  float v = out[(size_t)node * 128 + tid] * g_sc2[tid] + g_sh2[tid];
  float q = v * v;
#pragma unroll
  for (int o = 16; o; o >>= 1) q += __shfl_xor_sync(0xffffffffu, q, o);
  __shared__ float sq[2][4];
  int half = threadIdx.x >> 7;
  if ((tid & 31) == 0) sq[half][tid >> 5] = q;
  __syncthreads();
  float tot = sq[half][0] + sq[half][1] + sq[half][2] + sq[half][3];
  float r = 1.f / fmaxf(sqrtf(tot), 1e-12f);
  out[(size_t)node * 128 + tid] = v * r;
}

}  // namespace

extern "C" void kernel_launch(void* const* d_in, const int* in_sizes, int n_in,
                              void* d_out, int out_size) {
  const float* x        = (const float*)d_in[0];
  const float* W_in     = (const float*)d_in[1];
  const float* b_in     = (const float*)d_in[2];
  const float* gamma1   = (const float*)d_in[3];
  const float* beta1    = (const float*)d_in[4];
  const float* W1       = (const float*)d_in[5];
  const float* att_src1 = (const float*)d_in[6];
  const float* att_dst1 = (const float*)d_in[7];
  const float* bias1    = (const float*)d_in[8];
  const float* W2       = (const float*)d_in[9];
  const float* att_src2 = (const float*)d_in[10];
  const float* att_dst2 = (const float*)d_in[11];
  const float* bias2    = (const float*)d_in[12];
  const float* W_skip   = (const float*)d_in[13];
  const float* b_skip   = (const float*)d_in[14];
  const float* gamma2   = (const float*)d_in[15];
  const float* beta2    = (const float*)d_in[16];
  const void*  eidx     = d_in[17];
  float* out = (float*)d_out;

  const int GB = (NN + 127) / 128;   // 391
  const int SB = (NN + 511) / 512;   // 98
  const int AB = (NN + 7) / 8;       // 6250

  // --- GEMM chain first (independent of CSR); launch idx 3 = gemm2 for profiling ---
  k_gemm_tc<KIN, M_BIAS | M_LEAKY, 0><<<GB, 256>>>(x, W_in, b_in, nullptr);  // 0
  k_colstats<1><<<SB, 256>>>(nullptr);                                        // 1
  k_bnfin<1><<<1, 128>>>(gamma1, beta1);                                      // 2
  k_gemm_tc<128, M_BNA, 1><<<GB, 256>>>(nullptr, W1, nullptr, nullptr);       // 3 (profiled)
  k_att<8><<<NN / 2, 256>>>(att_src1, att_dst1);                              // 4

  // --- CSR build ---
  k_zero<<<(NN + 255) / 256, 256>>>(eidx);
  k_edges<<<(NE + 255) / 256, 256>>>(eidx);
  k_scan<<<NB, 1024>>>();
  k_scatter<<<(NE + 255) / 256, 256>>>();

  // --- layer 1 aggregate, layer 2, merge ---
  k_gat<8, true><<<AB, 256>>>(bias1);
  k_gemm_tc<128, 0, 2><<<GB, 256>>>(nullptr, W2, nullptr, nullptr);
  k_att<1><<<NN / 2, 256>>>(att_src2, att_dst2);
  k_gat<1, false><<<AB, 256>>>(bias2);
  k_gemm_tc<128, M_BIAS | M_ADDC, 3><<<GB, 256>>>(nullptr, W_skip, b_skip, out);
  k_colstats<2><<<SB, 256>>>(out);
  k_bnfin<2><<<1, 128>>>(gamma2, beta2);
  k_final<<<(NN + 1) / 2, 256>>>(out);
}